// round 1
// baseline (speedup 1.0000x reference)
#include <cuda_runtime.h>
#include <cstdint>

#define NN 300000
#define EE 600000
#define HH 128
#define GG 8192

// Scratch (device globals: allocation-free). 4 x 153.6MB + small.
__device__ float g_A[(size_t)NN * HH];   // h (layer input/output)
__device__ float g_B[(size_t)NN * HH];   // bond_agg -> aggr -> y2 (atomic accumulator, kept zeroed)
__device__ float g_C[(size_t)NN * HH];   // h_in
__device__ float g_D[(size_t)NN * HH];   // y1 (pre-BN1 GEMM1 output)
__device__ float g_deg[NN];
__device__ float g_pool[(size_t)GG * HH];
__device__ float g_stats[4 * HH];        // [sum1, sumsq1, sum2, sumsq2]
__device__ float g_bn[4 * HH];           // [mu1, rstd1, mu2, rstd2]

__device__ __forceinline__ void red_add_v4(float* p, float4 v) {
    asm volatile("red.global.add.v4.f32 [%0], {%1,%2,%3,%4};"
                 :: "l"(p), "f"(v.x), "f"(v.y), "f"(v.z), "f"(v.w) : "memory");
}

__global__ void k_init() {
    size_t stride = (size_t)gridDim.x * blockDim.x;
    size_t i0 = (size_t)blockIdx.x * blockDim.x + threadIdx.x;
    for (size_t i = i0; i < (size_t)NN * HH; i += stride) g_B[i] = 0.f;
    for (size_t i = i0; i < (size_t)NN; i += stride) g_deg[i] = 0.f;
    for (size_t i = i0; i < (size_t)GG * HH; i += stride) g_pool[i] = 0.f;
}

// AtomEncoder: h[n] = sum_f atom_emb[f][x[n,f]]
__global__ void k_atom(const int* __restrict__ x, const float* __restrict__ aemb) {
    int idx = blockIdx.x * blockDim.x + threadIdx.x;
    int n = idx >> 5; if (n >= NN) return;
    int c = (idx & 31) << 2;
    float4 acc = make_float4(0.f, 0.f, 0.f, 0.f);
#pragma unroll
    for (int f = 0; f < 9; f++) {
        int xi = __ldg(x + n * 9 + f);
        float4 e = *(const float4*)(aemb + ((size_t)(f * 128 + xi) * HH + c));
        acc.x += e.x; acc.y += e.y; acc.z += e.z; acc.w += e.w;
    }
    *(float4*)(g_A + (size_t)n * HH + c) = acc;
}

__global__ void k_deg(const int* __restrict__ row) {
    int e = blockIdx.x * blockDim.x + threadIdx.x;
    if (e < EE) atomicAdd(&g_deg[__ldg(row + e)], 1.f);
}

// BondEncoder + scatter-add into g_B[row[e]]
__global__ void k_bond(const int* __restrict__ row, const int* __restrict__ eattr,
                       const float* __restrict__ bemb) {
    int idx = blockIdx.x * blockDim.x + threadIdx.x;
    int e = idx >> 5; if (e >= EE) return;
    int c = (idx & 31) << 2;
    int a0 = __ldg(eattr + e * 3 + 0);
    int a1 = __ldg(eattr + e * 3 + 1);
    int a2 = __ldg(eattr + e * 3 + 2);
    const float4 v0 = *(const float4*)(bemb + ((size_t)a0 * HH + c));
    const float4 v1 = *(const float4*)(bemb + ((size_t)(8 + a1) * HH + c));
    const float4 v2 = *(const float4*)(bemb + ((size_t)(16 + a2) * HH + c));
    float4 s = make_float4(v0.x + v1.x + v2.x, v0.y + v1.y + v2.y,
                           v0.z + v1.z + v2.z, v0.w + v1.w + v2.w);
    red_add_v4(g_B + (size_t)__ldg(row + e) * HH + c, s);
}

// h_in = h + bond_agg * 1/(deg+1); rezero g_B; zero stats buffer
__global__ void k_hin() {
    int idx = blockIdx.x * blockDim.x + threadIdx.x;
    if (idx < 4 * HH) g_stats[idx] = 0.f;
    int n = idx >> 5; if (n >= NN) return;
    int c = (idx & 31) << 2;
    float inv = 1.f / (g_deg[n] + 1.f);
    float4 a = *(const float4*)(g_A + (size_t)n * HH + c);
    float4 b = *(const float4*)(g_B + (size_t)n * HH + c);
    float4 r = make_float4(fmaf(b.x, inv, a.x), fmaf(b.y, inv, a.y),
                           fmaf(b.z, inv, a.z), fmaf(b.w, inv, a.w));
    *(float4*)(g_C + (size_t)n * HH + c) = r;
    *(float4*)(g_B + (size_t)n * HH + c) = make_float4(0.f, 0.f, 0.f, 0.f);
}

// aggr: g_B[col[e]] += h_in[row[e]]
__global__ void k_aggr(const int* __restrict__ row, const int* __restrict__ col) {
    int idx = blockIdx.x * blockDim.x + threadIdx.x;
    int e = idx >> 5; if (e >= EE) return;
    int c = (idx & 31) << 2;
    float4 v = *(const float4*)(g_C + (size_t)__ldg(row + e) * HH + c);
    red_add_v4(g_B + (size_t)__ldg(col + e) * HH + c, v);
}

// GEMM [NN,128] x [128,128] + bias, fused input transform + BN-stat epilogue.
// MODE 1: in = (1+eps)*g_C + g_B, out = g_D, stats -> g_stats[0:256]
// MODE 2: in = relu(bn1(g_D)),    out = g_B, stats -> g_stats[256:512]
template<int MODE>
__global__ void __launch_bounds__(256, 2)
k_gemm(const float* __restrict__ W, const float* __restrict__ bias,
       const float* __restrict__ epsl_p,
       const float* __restrict__ bg, const float* __restrict__ bb) {
    __shared__ float As[16][HH];
    __shared__ float Ws[16][HH];
    const int tid = threadIdx.x;
    const int tc = tid & 15, tr = tid >> 4;
    const int m0 = blockIdx.x * 128;
    const int lr = tid >> 1;
    const int gb = (tid & 1) * 2;
    const int grow = m0 + lr;

    float acc[8][8];
#pragma unroll
    for (int i = 0; i < 8; i++)
#pragma unroll
        for (int j = 0; j < 8; j++) acc[i][j] = 0.f;

    float epsl = 0.f;
    if (MODE == 1) epsl = 1.f + __ldg(epsl_p);

    for (int kc = 0; kc < HH; kc += 16) {
        // W tile: 16 x 128
#pragma unroll
        for (int it = 0; it < 2; it++) {
            int q = tid + it * 256;
            int k = q >> 5, j = (q & 31) << 2;
            *(float4*)&Ws[k][j] = *(const float4*)(W + (size_t)(kc + k) * HH + j);
        }
        // A tile: 128 rows x 16 k, transformed on the fly, stored k-major
#pragma unroll
        for (int it = 0; it < 2; it++) {
            int g = gb + it;
            int f = kc + g * 4;
            float4 v = make_float4(0.f, 0.f, 0.f, 0.f);
            if (grow < NN) {
                if (MODE == 1) {
                    float4 cv = *(const float4*)(g_C + (size_t)grow * HH + f);
                    float4 bv = *(const float4*)(g_B + (size_t)grow * HH + f);
                    v.x = fmaf(epsl, cv.x, bv.x);
                    v.y = fmaf(epsl, cv.y, bv.y);
                    v.z = fmaf(epsl, cv.z, bv.z);
                    v.w = fmaf(epsl, cv.w, bv.w);
                } else {
                    float4 y = *(const float4*)(g_D + (size_t)grow * HH + f);
                    float s0 = __ldg(bg + f + 0) * g_bn[HH + f + 0];
                    float s1 = __ldg(bg + f + 1) * g_bn[HH + f + 1];
                    float s2 = __ldg(bg + f + 2) * g_bn[HH + f + 2];
                    float s3 = __ldg(bg + f + 3) * g_bn[HH + f + 3];
                    v.x = fmaxf(fmaf(s0, y.x - g_bn[f + 0], __ldg(bb + f + 0)), 0.f);
                    v.y = fmaxf(fmaf(s1, y.y - g_bn[f + 1], __ldg(bb + f + 1)), 0.f);
                    v.z = fmaxf(fmaf(s2, y.z - g_bn[f + 2], __ldg(bb + f + 2)), 0.f);
                    v.w = fmaxf(fmaf(s3, y.w - g_bn[f + 3], __ldg(bb + f + 3)), 0.f);
                }
            }
            As[g * 4 + 0][lr] = v.x;
            As[g * 4 + 1][lr] = v.y;
            As[g * 4 + 2][lr] = v.z;
            As[g * 4 + 3][lr] = v.w;
        }
        __syncthreads();
#pragma unroll
        for (int kk = 0; kk < 16; kk++) {
            float a[8], w[8];
            *(float4*)&a[0] = *(const float4*)&As[kk][tr * 8];
            *(float4*)&a[4] = *(const float4*)&As[kk][tr * 8 + 4];
            *(float4*)&w[0] = *(const float4*)&Ws[kk][tc * 8];
            *(float4*)&w[4] = *(const float4*)&Ws[kk][tc * 8 + 4];
#pragma unroll
            for (int i = 0; i < 8; i++)
#pragma unroll
                for (int j = 0; j < 8; j++)
                    acc[i][j] = fmaf(a[i], w[j], acc[i][j]);
        }
        __syncthreads();
    }

    float bset[8];
#pragma unroll
    for (int j = 0; j < 8; j++) bset[j] = __ldg(bias + tc * 8 + j);
    float cs[8], cq[8];
#pragma unroll
    for (int j = 0; j < 8; j++) { cs[j] = 0.f; cq[j] = 0.f; }
    float* outp = (MODE == 1) ? g_D : g_B;
#pragma unroll
    for (int i = 0; i < 8; i++) {
        int r = m0 + tr * 8 + i;
        if (r < NN) {
            float o[8];
#pragma unroll
            for (int j = 0; j < 8; j++) {
                o[j] = acc[i][j] + bset[j];
                cs[j] += o[j];
                cq[j] += o[j] * o[j];
            }
            *(float4*)(outp + (size_t)r * HH + tc * 8)     = make_float4(o[0], o[1], o[2], o[3]);
            *(float4*)(outp + (size_t)r * HH + tc * 8 + 4) = make_float4(o[4], o[5], o[6], o[7]);
        }
    }
    float* st = g_stats + ((MODE == 1) ? 0 : 2 * HH);
#pragma unroll
    for (int j = 0; j < 8; j++) {
        atomicAdd(st + tc * 8 + j, cs[j]);
        atomicAdd(st + HH + tc * 8 + j, cq[j]);
    }
}

__global__ void k_bnstat(int set) {
    int j = threadIdx.x;
    float s  = g_stats[set * 2 * HH + j];
    float sq = g_stats[set * 2 * HH + HH + j];
    float mu = s * (1.f / (float)NN);
    float var = sq * (1.f / (float)NN) - mu * mu;
    g_bn[set * 2 * HH + j] = mu;
    g_bn[set * 2 * HH + HH + j] = rsqrtf(var + 1e-5f);
}

// h = bn2(y2) (+relu); rezero g_B for next layer's scatters
__global__ void k_bnapply(const float* __restrict__ bg, const float* __restrict__ bb, int relu) {
    int idx = blockIdx.x * blockDim.x + threadIdx.x;
    int n = idx >> 5; if (n >= NN) return;
    int c = (idx & 31) << 2;
    float4 y = *(const float4*)(g_B + (size_t)n * HH + c);
    float s0 = __ldg(bg + c + 0) * g_bn[3 * HH + c + 0];
    float s1 = __ldg(bg + c + 1) * g_bn[3 * HH + c + 1];
    float s2 = __ldg(bg + c + 2) * g_bn[3 * HH + c + 2];
    float s3 = __ldg(bg + c + 3) * g_bn[3 * HH + c + 3];
    float4 o;
    o.x = fmaf(s0, y.x - g_bn[2 * HH + c + 0], __ldg(bb + c + 0));
    o.y = fmaf(s1, y.y - g_bn[2 * HH + c + 1], __ldg(bb + c + 1));
    o.z = fmaf(s2, y.z - g_bn[2 * HH + c + 2], __ldg(bb + c + 2));
    o.w = fmaf(s3, y.w - g_bn[2 * HH + c + 3], __ldg(bb + c + 3));
    if (relu) {
        o.x = fmaxf(o.x, 0.f); o.y = fmaxf(o.y, 0.f);
        o.z = fmaxf(o.z, 0.f); o.w = fmaxf(o.w, 0.f);
    }
    *(float4*)(g_A + (size_t)n * HH + c) = o;
    *(float4*)(g_B + (size_t)n * HH + c) = make_float4(0.f, 0.f, 0.f, 0.f);
}

__global__ void k_pool(const int* __restrict__ batch) {
    int idx = blockIdx.x * blockDim.x + threadIdx.x;
    int n = idx >> 5; if (n >= NN) return;
    int c = (idx & 31) << 2;
    float4 v = *(const float4*)(g_A + (size_t)n * HH + c);
    red_add_v4(g_pool + (size_t)__ldg(batch + n) * HH + c, v);
}

__global__ void k_final(const float* __restrict__ cw1, const float* __restrict__ cb1,
                        const float* __restrict__ cw2, const float* __restrict__ cb2,
                        float* __restrict__ out) {
    __shared__ float p[HH];
    __shared__ float rb[4];
    int j = threadIdx.x;
    p[j] = g_pool[(size_t)blockIdx.x * HH + j];
    __syncthreads();
    float acc = __ldg(cb1 + j);
#pragma unroll 8
    for (int i = 0; i < HH; i++)
        acc = fmaf(p[i], __ldg(cw1 + i * HH + j), acc);
    float v = fmaxf(acc, 0.f) * __ldg(cw2 + j);
#pragma unroll
    for (int off = 16; off > 0; off >>= 1)
        v += __shfl_down_sync(0xffffffffu, v, off);
    if ((j & 31) == 0) rb[j >> 5] = v;
    __syncthreads();
    if (j == 0) out[blockIdx.x] = rb[0] + rb[1] + rb[2] + rb[3] + __ldg(cb2);
}

extern "C" void kernel_launch(void* const* d_in, const int* in_sizes, int n_in,
                              void* d_out, int out_size) {
    const int*   x     = (const int*)d_in[0];
    const int*   ei    = (const int*)d_in[1];
    const int*   ea    = (const int*)d_in[2];
    const int*   batch = (const int*)d_in[3];
    const float* aemb  = (const float*)d_in[4];
    const float* bemb  = (const float*)d_in[5];
    const float* eps   = (const float*)d_in[6];
    const float* w1    = (const float*)d_in[7];
    const float* b1    = (const float*)d_in[8];
    const float* bn1g  = (const float*)d_in[9];
    const float* bn1b  = (const float*)d_in[10];
    const float* w2    = (const float*)d_in[11];
    const float* b2    = (const float*)d_in[12];
    const float* bng   = (const float*)d_in[13];
    const float* bnb   = (const float*)d_in[14];
    const float* cw1   = (const float*)d_in[15];
    const float* cb1   = (const float*)d_in[16];
    const float* cw2   = (const float*)d_in[17];
    const float* cb2   = (const float*)d_in[18];
    float* out = (float*)d_out;
    const int* row = ei;
    const int* col = ei + EE;

    const int NT = 256;
    const int gridNH = (NN * 32 + NT - 1) / NT;   // 37500
    const int gridEH = (EE * 32 + NT - 1) / NT;   // 75000

    k_init<<<4096, NT>>>();
    k_atom<<<gridNH, NT>>>(x, aemb);
    k_deg<<<(EE + NT - 1) / NT, NT>>>(row);
    for (int l = 0; l < 5; l++) {
        k_bond<<<gridEH, NT>>>(row, ea, bemb + (size_t)l * 3 * 8 * HH);
        k_hin<<<gridNH, NT>>>();
        k_aggr<<<gridEH, NT>>>(row, col);
        k_gemm<1><<<(NN + 127) / 128, NT>>>(w1 + (size_t)l * HH * HH, b1 + l * HH,
                                            eps + l, nullptr, nullptr);
        k_bnstat<<<1, HH>>>(0);
        k_gemm<2><<<(NN + 127) / 128, NT>>>(w2 + (size_t)l * HH * HH, b2 + l * HH,
                                            nullptr, bn1g + l * HH, bn1b + l * HH);
        k_bnstat<<<1, HH>>>(1);
        k_bnapply<<<gridNH, NT>>>(bng + l * HH, bnb + l * HH, (l < 4) ? 1 : 0);
    }
    k_pool<<<gridNH, NT>>>(batch);
    k_final<<<GG, HH>>>(cw1, cb1, cw2, cb2, out);
}

// round 2
// speedup vs baseline: 5.5475x; 5.5475x over previous
#include <cuda_runtime.h>
#include <cstdint>

#define NN 300000
#define EE 600000
#define HH 128
#define GG 8192

// Scratch (device globals: allocation-free).
__device__ float g_P[(size_t)NN * HH];    // prev-layer raw output (atom enc / y2 pre-BN)
__device__ float g_HIN[(size_t)NN * HH];  // h_in
__device__ float g_ACC[(size_t)NN * HH];  // atomic accumulator (kept zeroed)
__device__ float g_Y1[(size_t)NN * HH];   // y1 (pre-BN1 GEMM1 output)
__device__ float g_deg[NN];
__device__ float g_pool[(size_t)GG * HH];
__device__ float g_stats[4 * HH];         // [sum1, sumsq1, sum2, sumsq2]
__device__ float g_bn[4 * HH];            // [mu1, rstd1, mu2, rstd2]

__device__ __forceinline__ void red_add_v4(float* p, float4 v) {
    asm volatile("red.global.add.v4.f32 [%0], {%1,%2,%3,%4};"
                 :: "l"(p), "f"(v.x), "f"(v.y), "f"(v.z), "f"(v.w) : "memory");
}

__global__ void k_init() {
    size_t stride = (size_t)gridDim.x * blockDim.x;
    size_t i0 = (size_t)blockIdx.x * blockDim.x + threadIdx.x;
    for (size_t i = i0; i < (size_t)NN * HH; i += stride) g_ACC[i] = 0.f;
    for (size_t i = i0; i < (size_t)NN; i += stride) g_deg[i] = 0.f;
    for (size_t i = i0; i < (size_t)GG * HH; i += stride) g_pool[i] = 0.f;
}

// AtomEncoder: P[n] = sum_f atom_emb[f][x[n,f]]
__global__ void k_atom(const int* __restrict__ x, const float* __restrict__ aemb) {
    int idx = blockIdx.x * blockDim.x + threadIdx.x;
    int n = idx >> 5; if (n >= NN) return;
    int c = (idx & 31) << 2;
    float4 acc = make_float4(0.f, 0.f, 0.f, 0.f);
#pragma unroll
    for (int f = 0; f < 9; f++) {
        int xi = __ldg(x + n * 9 + f);
        float4 e = *(const float4*)(aemb + ((size_t)(f * 128 + xi) * HH + c));
        acc.x += e.x; acc.y += e.y; acc.z += e.z; acc.w += e.w;
    }
    *(float4*)(g_P + (size_t)n * HH + c) = acc;
}

__global__ void k_deg(const int* __restrict__ row) {
    int e = blockIdx.x * blockDim.x + threadIdx.x;
    if (e < EE) atomicAdd(&g_deg[__ldg(row + e)], 1.f);
}

// BondEncoder + scatter-add into ACC[row[e]]
__global__ void k_bond(const int* __restrict__ row, const int* __restrict__ eattr,
                       const float* __restrict__ bemb) {
    int idx = blockIdx.x * blockDim.x + threadIdx.x;
    int e = idx >> 5; if (e >= EE) return;
    int c = (idx & 31) << 2;
    int a0 = __ldg(eattr + e * 3 + 0);
    int a1 = __ldg(eattr + e * 3 + 1);
    int a2 = __ldg(eattr + e * 3 + 2);
    const float4 v0 = *(const float4*)(bemb + ((size_t)a0 * HH + c));
    const float4 v1 = *(const float4*)(bemb + ((size_t)(8 + a1) * HH + c));
    const float4 v2 = *(const float4*)(bemb + ((size_t)(16 + a2) * HH + c));
    float4 s = make_float4(v0.x + v1.x + v2.x, v0.y + v1.y + v2.y,
                           v0.z + v1.z + v2.z, v0.w + v1.w + v2.w);
    red_add_v4(g_ACC + (size_t)__ldg(row + e) * HH + c, s);
}

// HIN = act(P) + ACC * 1/(deg+1); rezero ACC; zero stats.
// FIRST=1: act = identity. FIRST=0: act = relu(bn2(P)) using g_bn set 1 + bg/bb.
template<int FIRST>
__global__ void k_hin(const float* __restrict__ bg, const float* __restrict__ bb) {
    int idx = blockIdx.x * blockDim.x + threadIdx.x;
    if (idx < 4 * HH) g_stats[idx] = 0.f;
    int n = idx >> 5; if (n >= NN) return;
    int c = (idx & 31) << 2;
    float inv = 1.f / (g_deg[n] + 1.f);
    float4 p = *(const float4*)(g_P + (size_t)n * HH + c);
    if (!FIRST) {
        float s0 = __ldg(bg + c + 0) * g_bn[3 * HH + c + 0];
        float s1 = __ldg(bg + c + 1) * g_bn[3 * HH + c + 1];
        float s2 = __ldg(bg + c + 2) * g_bn[3 * HH + c + 2];
        float s3 = __ldg(bg + c + 3) * g_bn[3 * HH + c + 3];
        p.x = fmaxf(fmaf(s0, p.x - g_bn[2 * HH + c + 0], __ldg(bb + c + 0)), 0.f);
        p.y = fmaxf(fmaf(s1, p.y - g_bn[2 * HH + c + 1], __ldg(bb + c + 1)), 0.f);
        p.z = fmaxf(fmaf(s2, p.z - g_bn[2 * HH + c + 2], __ldg(bb + c + 2)), 0.f);
        p.w = fmaxf(fmaf(s3, p.w - g_bn[2 * HH + c + 3], __ldg(bb + c + 3)), 0.f);
    }
    float4 b = *(const float4*)(g_ACC + (size_t)n * HH + c);
    float4 r = make_float4(fmaf(b.x, inv, p.x), fmaf(b.y, inv, p.y),
                           fmaf(b.z, inv, p.z), fmaf(b.w, inv, p.w));
    *(float4*)(g_HIN + (size_t)n * HH + c) = r;
    *(float4*)(g_ACC + (size_t)n * HH + c) = make_float4(0.f, 0.f, 0.f, 0.f);
}

// aggr: ACC[col[e]] += HIN[row[e]]
__global__ void k_aggr(const int* __restrict__ row, const int* __restrict__ col) {
    int idx = blockIdx.x * blockDim.x + threadIdx.x;
    int e = idx >> 5; if (e >= EE) return;
    int c = (idx & 31) << 2;
    float4 v = *(const float4*)(g_HIN + (size_t)__ldg(row + e) * HH + c);
    red_add_v4(g_ACC + (size_t)__ldg(col + e) * HH + c, v);
}

// GEMM [NN,128] x [128,128] + bias, fused input transform + BN-stat epilogue.
// MODE 1: in = (1+eps)*HIN + ACC (rezero ACC), out = Y1, stats -> g_stats[0:256]
// MODE 2: in = relu(bn1(Y1)),                  out = P,  stats -> g_stats[256:512]
template<int MODE>
__global__ void __launch_bounds__(256, 2)
k_gemm(const float* __restrict__ W, const float* __restrict__ bias,
       const float* __restrict__ epsp,
       const float* __restrict__ bg, const float* __restrict__ bb) {
    __shared__ float As[16][HH];
    __shared__ float Ws[16][HH];
    __shared__ float sc[HH], sh[HH];
    const int tid = threadIdx.x;
    const int tc = tid & 15, tr = tid >> 4;
    const int m0 = blockIdx.x * 128;
    const int lr = tid >> 1;
    const int gb = (tid & 1) * 2;
    const int grow = m0 + lr;
    const bool rok = grow < NN;

    if (MODE == 2) {
        if (tid < HH) {
            float s = __ldg(bg + tid) * g_bn[HH + tid];
            sc[tid] = s;
            sh[tid] = __ldg(bb + tid) - s * g_bn[tid];
        }
        __syncthreads();
    }
    const float epsl = (MODE == 1) ? (1.f + __ldg(epsp)) : 0.f;

    float acc[8][8];
#pragma unroll
    for (int i = 0; i < 8; i++)
#pragma unroll
        for (int j = 0; j < 8; j++) acc[i][j] = 0.f;

    float4 rA[2], rW[2];

    auto loadW = [&](int kc) {
#pragma unroll
        for (int it = 0; it < 2; it++) {
            int q = tid + it * 256;
            int k = q >> 5, j = (q & 31) << 2;
            rW[it] = *(const float4*)(W + (size_t)(kc + k) * HH + j);
        }
    };
    auto loadA = [&](int kc) {
#pragma unroll
        for (int it = 0; it < 2; it++) {
            int g = gb + it;
            int f = kc + g * 4;
            float4 v = make_float4(0.f, 0.f, 0.f, 0.f);
            if (rok) {
                if (MODE == 1) {
                    float4 cv = *(const float4*)(g_HIN + (size_t)grow * HH + f);
                    float4 bv = *(const float4*)(g_ACC + (size_t)grow * HH + f);
                    v.x = fmaf(epsl, cv.x, bv.x);
                    v.y = fmaf(epsl, cv.y, bv.y);
                    v.z = fmaf(epsl, cv.z, bv.z);
                    v.w = fmaf(epsl, cv.w, bv.w);
                    *(float4*)(g_ACC + (size_t)grow * HH + f) =
                        make_float4(0.f, 0.f, 0.f, 0.f);
                } else {
                    float4 y = *(const float4*)(g_Y1 + (size_t)grow * HH + f);
                    v.x = fmaxf(fmaf(sc[f + 0], y.x, sh[f + 0]), 0.f);
                    v.y = fmaxf(fmaf(sc[f + 1], y.y, sh[f + 1]), 0.f);
                    v.z = fmaxf(fmaf(sc[f + 2], y.z, sh[f + 2]), 0.f);
                    v.w = fmaxf(fmaf(sc[f + 3], y.w, sh[f + 3]), 0.f);
                }
            }
            rA[it] = v;
        }
    };

    loadW(0);
    loadA(0);

#pragma unroll
    for (int kc = 0; kc < HH; kc += 16) {
        // commit prefetched regs to smem
#pragma unroll
        for (int it = 0; it < 2; it++) {
            int q = tid + it * 256;
            int k = q >> 5, j = (q & 31) << 2;
            *(float4*)&Ws[k][j] = rW[it];
        }
#pragma unroll
        for (int it = 0; it < 2; it++) {
            int g = gb + it;
            As[g * 4 + 0][lr] = rA[it].x;
            As[g * 4 + 1][lr] = rA[it].y;
            As[g * 4 + 2][lr] = rA[it].z;
            As[g * 4 + 3][lr] = rA[it].w;
        }
        __syncthreads();
        if (kc < HH - 16) {
            loadW(kc + 16);
            loadA(kc + 16);
        }
#pragma unroll
        for (int kk = 0; kk < 16; kk++) {
            float a[8], w[8];
            *(float4*)&a[0] = *(const float4*)&As[kk][tr * 8];
            *(float4*)&a[4] = *(const float4*)&As[kk][tr * 8 + 4];
            *(float4*)&w[0] = *(const float4*)&Ws[kk][tc * 8];
            *(float4*)&w[4] = *(const float4*)&Ws[kk][tc * 8 + 4];
#pragma unroll
            for (int i = 0; i < 8; i++)
#pragma unroll
                for (int j = 0; j < 8; j++)
                    acc[i][j] = fmaf(a[i], w[j], acc[i][j]);
        }
        __syncthreads();
    }

    float bset[8];
#pragma unroll
    for (int j = 0; j < 8; j++) bset[j] = __ldg(bias + tc * 8 + j);
    float cs[8], cq[8];
#pragma unroll
    for (int j = 0; j < 8; j++) { cs[j] = 0.f; cq[j] = 0.f; }
    float* outp = (MODE == 1) ? g_Y1 : g_P;
#pragma unroll
    for (int i = 0; i < 8; i++) {
        int r = m0 + tr * 8 + i;
        if (r < NN) {
            float o[8];
#pragma unroll
            for (int j = 0; j < 8; j++) {
                o[j] = acc[i][j] + bset[j];
                cs[j] += o[j];
                cq[j] += o[j] * o[j];
            }
            *(float4*)(outp + (size_t)r * HH + tc * 8)     = make_float4(o[0], o[1], o[2], o[3]);
            *(float4*)(outp + (size_t)r * HH + tc * 8 + 4) = make_float4(o[4], o[5], o[6], o[7]);
        }
    }
    // Stats: smem tree-reduce over tr, then 1 RED per column per block.
    float* red = &As[0][0];   // 2048 floats, free after compute loop
    float* st = g_stats + ((MODE == 1) ? 0 : 2 * HH);
#pragma unroll
    for (int j = 0; j < 8; j++) red[tr * HH + tc * 8 + j] = cs[j];
    __syncthreads();
    if (tid < HH) {
        float s = 0.f;
#pragma unroll
        for (int t = 0; t < 16; t++) s += red[t * HH + tid];
        atomicAdd(st + tid, s);
    }
    __syncthreads();
#pragma unroll
    for (int j = 0; j < 8; j++) red[tr * HH + tc * 8 + j] = cq[j];
    __syncthreads();
    if (tid < HH) {
        float s = 0.f;
#pragma unroll
        for (int t = 0; t < 16; t++) s += red[t * HH + tid];
        atomicAdd(st + HH + tid, s);
    }
}

__global__ void k_bnstat(int set) {
    int j = threadIdx.x;
    float s  = g_stats[set * 2 * HH + j];
    float sq = g_stats[set * 2 * HH + HH + j];
    float mu = s * (1.f / (float)NN);
    float var = sq * (1.f / (float)NN) - mu * mu;
    g_bn[set * 2 * HH + j] = mu;
    g_bn[set * 2 * HH + HH + j] = rsqrtf(var + 1e-5f);
}

// pool: applies bn2 of last layer (no relu), scatters to g_pool
__global__ void k_pool(const int* __restrict__ batch,
                       const float* __restrict__ bg, const float* __restrict__ bb) {
    int idx = blockIdx.x * blockDim.x + threadIdx.x;
    int n = idx >> 5; if (n >= NN) return;
    int c = (idx & 31) << 2;
    float4 y = *(const float4*)(g_P + (size_t)n * HH + c);
    float s0 = __ldg(bg + c + 0) * g_bn[3 * HH + c + 0];
    float s1 = __ldg(bg + c + 1) * g_bn[3 * HH + c + 1];
    float s2 = __ldg(bg + c + 2) * g_bn[3 * HH + c + 2];
    float s3 = __ldg(bg + c + 3) * g_bn[3 * HH + c + 3];
    float4 o;
    o.x = fmaf(s0, y.x - g_bn[2 * HH + c + 0], __ldg(bb + c + 0));
    o.y = fmaf(s1, y.y - g_bn[2 * HH + c + 1], __ldg(bb + c + 1));
    o.z = fmaf(s2, y.z - g_bn[2 * HH + c + 2], __ldg(bb + c + 2));
    o.w = fmaf(s3, y.w - g_bn[2 * HH + c + 3], __ldg(bb + c + 3));
    red_add_v4(g_pool + (size_t)__ldg(batch + n) * HH + c, o);
}

__global__ void k_final(const float* __restrict__ cw1, const float* __restrict__ cb1,
                        const float* __restrict__ cw2, const float* __restrict__ cb2,
                        float* __restrict__ out) {
    __shared__ float p[HH];
    __shared__ float rb[4];
    int j = threadIdx.x;
    p[j] = g_pool[(size_t)blockIdx.x * HH + j];
    __syncthreads();
    float acc = __ldg(cb1 + j);
#pragma unroll 8
    for (int i = 0; i < HH; i++)
        acc = fmaf(p[i], __ldg(cw1 + i * HH + j), acc);
    float v = fmaxf(acc, 0.f) * __ldg(cw2 + j);
#pragma unroll
    for (int off = 16; off > 0; off >>= 1)
        v += __shfl_down_sync(0xffffffffu, v, off);
    if ((j & 31) == 0) rb[j >> 5] = v;
    __syncthreads();
    if (j == 0) out[blockIdx.x] = rb[0] + rb[1] + rb[2] + rb[3] + __ldg(cb2);
}

extern "C" void kernel_launch(void* const* d_in, const int* in_sizes, int n_in,
                              void* d_out, int out_size) {
    const int*   x     = (const int*)d_in[0];
    const int*   ei    = (const int*)d_in[1];
    const int*   ea    = (const int*)d_in[2];
    const int*   batch = (const int*)d_in[3];
    const float* aemb  = (const float*)d_in[4];
    const float* bemb  = (const float*)d_in[5];
    const float* eps   = (const float*)d_in[6];
    const float* w1    = (const float*)d_in[7];
    const float* b1    = (const float*)d_in[8];
    const float* bn1g  = (const float*)d_in[9];
    const float* bn1b  = (const float*)d_in[10];
    const float* w2    = (const float*)d_in[11];
    const float* b2    = (const float*)d_in[12];
    const float* bng   = (const float*)d_in[13];
    const float* bnb   = (const float*)d_in[14];
    const float* cw1   = (const float*)d_in[15];
    const float* cb1   = (const float*)d_in[16];
    const float* cw2   = (const float*)d_in[17];
    const float* cb2   = (const float*)d_in[18];
    float* out = (float*)d_out;
    const int* row = ei;
    const int* col = ei + EE;

    const int NT = 256;
    const int gridNH = (NN * 32 + NT - 1) / NT;   // 37500
    const int gridEH = (EE * 32 + NT - 1) / NT;   // 75000
    const int gridGEMM = (NN + 127) / 128;        // 2344

    k_init<<<4096, NT>>>();
    k_atom<<<gridNH, NT>>>(x, aemb);
    k_deg<<<(EE + NT - 1) / NT, NT>>>(row);
    for (int l = 0; l < 5; l++) {
        k_bond<<<gridEH, NT>>>(row, ea, bemb + (size_t)l * 3 * 8 * HH);
        if (l == 0)
            k_hin<1><<<gridNH, NT>>>(nullptr, nullptr);
        else
            k_hin<0><<<gridNH, NT>>>(bng + (l - 1) * HH, bnb + (l - 1) * HH);
        k_aggr<<<gridEH, NT>>>(row, col);
        k_gemm<1><<<gridGEMM, NT>>>(w1 + (size_t)l * HH * HH, b1 + l * HH,
                                    eps + l, nullptr, nullptr);
        k_bnstat<<<1, HH>>>(0);
        k_gemm<2><<<gridGEMM, NT>>>(w2 + (size_t)l * HH * HH, b2 + l * HH,
                                    nullptr, bn1g + l * HH, bn1b + l * HH);
        k_bnstat<<<1, HH>>>(1);
    }
    k_pool<<<gridNH, NT>>>(batch, bng + 4 * HH, bnb + 4 * HH);
    k_final<<<GG, HH>>>(cw1, cb1, cw2, cb2, out);
}

// round 4
// speedup vs baseline: 7.6585x; 1.3805x over previous
#include <cuda_runtime.h>
#include <cuda_bf16.h>
#include <cstdint>

#define NN 300000
#define EE 600000
#define HH 128
#define GG 8192

// ---------------- scratch (device globals: allocation-free) ----------------
__device__ float g_P[(size_t)NN * HH];    // prev-layer raw output (atom enc / y2 pre-BN)
__device__ float g_HIN[(size_t)NN * HH];  // h_in
__device__ float g_ACC[(size_t)NN * HH];  // atomic accumulator (kept zeroed)
__device__ float g_Y1[(size_t)NN * HH];   // y1 (pre-BN1 GEMM1 output)
__device__ float g_deg[NN];
__device__ float g_pool[(size_t)GG * HH];
__device__ float g_stats[4 * HH];         // [sum1, sumsq1, sum2, sumsq2]
__device__ float g_bn[4 * HH];            // [mu1, rstd1, mu2, rstd2]
// pre-split weights: 10 slots (2 per layer), [n][k] bf16 hi/lo
__device__ __nv_bfloat16 g_Wh[10 * HH * HH];
__device__ __nv_bfloat16 g_Wl[10 * HH * HH];

__device__ __forceinline__ void red_add_v4(float* p, float4 v) {
    asm volatile("red.global.add.v4.f32 [%0], {%1,%2,%3,%4};"
                 :: "l"(p), "f"(v.x), "f"(v.y), "f"(v.z), "f"(v.w) : "memory");
}
__device__ __forceinline__ uint32_t smem_u32(const void* p) {
    uint32_t a;
    asm("{ .reg .u64 t; cvta.to.shared.u64 t, %1; cvt.u32.u64 %0, t; }" : "=r"(a) : "l"(p));
    return a;
}
__device__ __forceinline__ void ldsm4(uint32_t* r, uint32_t addr) {
    asm volatile("ldmatrix.sync.aligned.m8n8.x4.shared.b16 {%0,%1,%2,%3}, [%4];"
                 : "=r"(r[0]), "=r"(r[1]), "=r"(r[2]), "=r"(r[3]) : "r"(addr));
}
__device__ __forceinline__ void mma16816(float* d, const uint32_t* a, const uint32_t* b) {
    asm volatile("mma.sync.aligned.m16n8k16.row.col.f32.bf16.bf16.f32 "
                 "{%0,%1,%2,%3}, {%4,%5,%6,%7}, {%8,%9}, {%0,%1,%2,%3};"
                 : "+f"(d[0]), "+f"(d[1]), "+f"(d[2]), "+f"(d[3])
                 : "r"(a[0]), "r"(a[1]), "r"(a[2]), "r"(a[3]), "r"(b[0]), "r"(b[1]));
}

// ---------------- element-wise / scatter kernels ----------------
__global__ void k_init() {
    size_t stride = (size_t)gridDim.x * blockDim.x;
    size_t i0 = (size_t)blockIdx.x * blockDim.x + threadIdx.x;
    for (size_t i = i0; i < (size_t)NN * HH; i += stride) g_ACC[i] = 0.f;
    for (size_t i = i0; i < (size_t)NN; i += stride) g_deg[i] = 0.f;
    for (size_t i = i0; i < (size_t)GG * HH; i += stride) g_pool[i] = 0.f;
}

// split all 10 weight matrices into bf16 hi/lo, transposed to [n][k]
__global__ void k_prepw(const float* __restrict__ w1, const float* __restrict__ w2) {
    int l = blockIdx.y;   // 0..9
    const float* W = (l < 5) ? (w1 + (size_t)l * HH * HH) : (w2 + (size_t)(l - 5) * HH * HH);
    int slot = (l < 5) ? (2 * l) : (2 * (l - 5) + 1);
    int q = blockIdx.x * 256 + threadIdx.x;   // 0..4095
    int k = q >> 5, n0 = (q & 31) * 4;
    float4 w = *(const float4*)(W + (size_t)k * HH + n0);
    float wv[4] = {w.x, w.y, w.z, w.w};
#pragma unroll
    for (int j = 0; j < 4; j++) {
        __nv_bfloat16 h = __float2bfloat16(wv[j]);
        size_t o = (size_t)slot * HH * HH + (size_t)(n0 + j) * HH + k;
        g_Wh[o] = h;
        g_Wl[o] = __float2bfloat16(wv[j] - __bfloat162float(h));
    }
}

__global__ void k_atom(const int* __restrict__ x, const float* __restrict__ aemb) {
    int idx = blockIdx.x * blockDim.x + threadIdx.x;
    int n = idx >> 5; if (n >= NN) return;
    int c = (idx & 31) << 2;
    float4 acc = make_float4(0.f, 0.f, 0.f, 0.f);
#pragma unroll
    for (int f = 0; f < 9; f++) {
        int xi = __ldg(x + n * 9 + f);
        float4 e = *(const float4*)(aemb + ((size_t)(f * 128 + xi) * HH + c));
        acc.x += e.x; acc.y += e.y; acc.z += e.z; acc.w += e.w;
    }
    *(float4*)(g_P + (size_t)n * HH + c) = acc;
}

__global__ void k_deg(const int* __restrict__ row) {
    int e = blockIdx.x * blockDim.x + threadIdx.x;
    if (e < EE) atomicAdd(&g_deg[__ldg(row + e)], 1.f);
}

__global__ void k_bond(const int* __restrict__ row, const int* __restrict__ eattr,
                       const float* __restrict__ bemb) {
    int idx = blockIdx.x * blockDim.x + threadIdx.x;
    int e = idx >> 5; if (e >= EE) return;
    int c = (idx & 31) << 2;
    int a0 = __ldg(eattr + e * 3 + 0);
    int a1 = __ldg(eattr + e * 3 + 1);
    int a2 = __ldg(eattr + e * 3 + 2);
    const float4 v0 = *(const float4*)(bemb + ((size_t)a0 * HH + c));
    const float4 v1 = *(const float4*)(bemb + ((size_t)(8 + a1) * HH + c));
    const float4 v2 = *(const float4*)(bemb + ((size_t)(16 + a2) * HH + c));
    float4 s = make_float4(v0.x + v1.x + v2.x, v0.y + v1.y + v2.y,
                           v0.z + v1.z + v2.z, v0.w + v1.w + v2.w);
    red_add_v4(g_ACC + (size_t)__ldg(row + e) * HH + c, s);
}

template<int FIRST>
__global__ void k_hin(const float* __restrict__ bg, const float* __restrict__ bb) {
    int idx = blockIdx.x * blockDim.x + threadIdx.x;
    if (idx < 4 * HH) g_stats[idx] = 0.f;
    int n = idx >> 5; if (n >= NN) return;
    int c = (idx & 31) << 2;
    float inv = 1.f / (g_deg[n] + 1.f);
    float4 p = *(const float4*)(g_P + (size_t)n * HH + c);
    if (!FIRST) {
        float s0 = __ldg(bg + c + 0) * g_bn[3 * HH + c + 0];
        float s1 = __ldg(bg + c + 1) * g_bn[3 * HH + c + 1];
        float s2 = __ldg(bg + c + 2) * g_bn[3 * HH + c + 2];
        float s3 = __ldg(bg + c + 3) * g_bn[3 * HH + c + 3];
        p.x = fmaxf(fmaf(s0, p.x - g_bn[2 * HH + c + 0], __ldg(bb + c + 0)), 0.f);
        p.y = fmaxf(fmaf(s1, p.y - g_bn[2 * HH + c + 1], __ldg(bb + c + 1)), 0.f);
        p.z = fmaxf(fmaf(s2, p.z - g_bn[2 * HH + c + 2], __ldg(bb + c + 2)), 0.f);
        p.w = fmaxf(fmaf(s3, p.w - g_bn[2 * HH + c + 3], __ldg(bb + c + 3)), 0.f);
    }
    float4 b = *(const float4*)(g_ACC + (size_t)n * HH + c);
    float4 r = make_float4(fmaf(b.x, inv, p.x), fmaf(b.y, inv, p.y),
                           fmaf(b.z, inv, p.z), fmaf(b.w, inv, p.w));
    *(float4*)(g_HIN + (size_t)n * HH + c) = r;
    *(float4*)(g_ACC + (size_t)n * HH + c) = make_float4(0.f, 0.f, 0.f, 0.f);
}

__global__ void k_aggr(const int* __restrict__ row, const int* __restrict__ col) {
    int idx = blockIdx.x * blockDim.x + threadIdx.x;
    int e = idx >> 5; if (e >= EE) return;
    int c = (idx & 31) << 2;
    float4 v = *(const float4*)(g_HIN + (size_t)__ldg(row + e) * HH + c);
    red_add_v4(g_ACC + (size_t)__ldg(col + e) * HH + c, v);
}

// ---------------- HMMA bf16-split GEMM ----------------
// D = A @ W + bias, fused input transform + BN-stat epilogue.
// MODE 1: A = (1+eps)*HIN + ACC (rezero ACC), out -> Y1, stats slot 0
// MODE 2: A = relu(bn1(Y1)),                  out -> P,  stats slot 1
// smem (dyn): Ah(34816) Al(34816) Bh(34816) Bl(34816) sS(2048) sQ(2048)
// padded stride: 136 halves (272 B) per row -> conflict-free ldmatrix.
#define PAD 136
#define GEMM_SMEM (4 * 34816 + 4096)

template<int MODE>
__global__ void __launch_bounds__(512, 1)
k_mma(int wslot, const float* __restrict__ bias,
      const float* __restrict__ epsp,
      const float* __restrict__ bg, const float* __restrict__ bb) {
    extern __shared__ char dsm[];
    __shared__ float s_sc[HH], s_sh[HH];

    const uint32_t su = smem_u32(dsm);
    const uint32_t Ah_u = su, Al_u = su + 34816;
    const uint32_t Bh_u = su + 69632, Bl_u = su + 104448;
    __nv_bfloat16* Ah = (__nv_bfloat16*)dsm;
    __nv_bfloat16* Al = (__nv_bfloat16*)(dsm + 34816);
    __nv_bfloat16* Bh = (__nv_bfloat16*)(dsm + 69632);
    __nv_bfloat16* Bl = (__nv_bfloat16*)(dsm + 104448);
    float* sS = (float*)(dsm + 139264);   // [4][128]
    float* sQ = (float*)(dsm + 141312);   // [4][128]

    const int tid = threadIdx.x;
    const int wid = tid >> 5, lane = tid & 31;
    const int wm = wid & 3, wn = wid >> 2;
    const int m0 = blockIdx.x * 128;

    if (MODE == 2 && tid < HH) {
        float s = __ldg(bg + tid) * g_bn[HH + tid];
        s_sc[tid] = s;
        s_sh[tid] = __ldg(bb + tid) - s * g_bn[tid];
    }
    const float epsl = (MODE == 1) ? (1.f + __ldg(epsp)) : 0.f;
    if (MODE == 2) __syncthreads();

    // ---- copy pre-split W [n][k] -> smem (coalesced 16B) ----
    const __nv_bfloat16* wh = g_Wh + (size_t)wslot * HH * HH;
    const __nv_bfloat16* wl = g_Wl + (size_t)wslot * HH * HH;
#pragma unroll
    for (int it = 0; it < 4; it++) {
        int q = it * 512 + tid;           // 0..2047
        int n = q >> 4, k0 = (q & 15) * 8;
        *(uint4*)(Bh + n * PAD + k0) = *(const uint4*)(wh + n * HH + k0);
        *(uint4*)(Bl + n * PAD + k0) = *(const uint4*)(wl + n * HH + k0);
    }
    // ---- load + transform + split A ----
#pragma unroll
    for (int it = 0; it < 8; it++) {
        int q = it * 512 + tid;
        int r = q >> 5, c0 = (q & 31) * 4;
        int grow = m0 + r;
        float4 v = make_float4(0.f, 0.f, 0.f, 0.f);
        if (grow < NN) {
            if (MODE == 1) {
                float4 cv = *(const float4*)(g_HIN + (size_t)grow * HH + c0);
                float4 bv = *(const float4*)(g_ACC + (size_t)grow * HH + c0);
                v.x = fmaf(epsl, cv.x, bv.x);
                v.y = fmaf(epsl, cv.y, bv.y);
                v.z = fmaf(epsl, cv.z, bv.z);
                v.w = fmaf(epsl, cv.w, bv.w);
                *(float4*)(g_ACC + (size_t)grow * HH + c0) = make_float4(0.f, 0.f, 0.f, 0.f);
            } else {
                float4 y = *(const float4*)(g_Y1 + (size_t)grow * HH + c0);
                v.x = fmaxf(fmaf(s_sc[c0 + 0], y.x, s_sh[c0 + 0]), 0.f);
                v.y = fmaxf(fmaf(s_sc[c0 + 1], y.y, s_sh[c0 + 1]), 0.f);
                v.z = fmaxf(fmaf(s_sc[c0 + 2], y.z, s_sh[c0 + 2]), 0.f);
                v.w = fmaxf(fmaf(s_sc[c0 + 3], y.w, s_sh[c0 + 3]), 0.f);
            }
        }
        float fv[4] = {v.x, v.y, v.z, v.w};
        __nv_bfloat16 hb[4], lb[4];
#pragma unroll
        for (int j = 0; j < 4; j++) {
            hb[j] = __float2bfloat16(fv[j]);
            lb[j] = __float2bfloat16(fv[j] - __bfloat162float(hb[j]));
        }
        *(uint2*)(Ah + r * PAD + c0) = *(uint2*)hb;
        *(uint2*)(Al + r * PAD + c0) = *(uint2*)lb;
    }
    __syncthreads();

    // ---- HMMA mainloop: K=128 in 8 steps of 16 ----
    float acc[2][4][4];
#pragma unroll
    for (int mi = 0; mi < 2; mi++)
#pragma unroll
        for (int nb = 0; nb < 4; nb++)
#pragma unroll
            for (int j = 0; j < 4; j++) acc[mi][nb][j] = 0.f;

    const int aRow = wm * 32 + (lane & 15);
    const int aKs = (lane >> 4) * 8;
    const int bN = wn * 32 + (lane >> 4) * 8 + (lane & 7);
    const int bKs = ((lane >> 3) & 1) * 8;

#pragma unroll
    for (int ks = 0; ks < 8; ks++) {
        uint32_t ah[2][4], al[2][4], bh[2][4], bl[2][4];
#pragma unroll
        for (int mi = 0; mi < 2; mi++) {
            uint32_t ra = (uint32_t)(((aRow + mi * 16) * PAD + ks * 16 + aKs) * 2);
            ldsm4(ah[mi], Ah_u + ra);
            ldsm4(al[mi], Al_u + ra);
        }
#pragma unroll
        for (int nb2 = 0; nb2 < 2; nb2++) {
            uint32_t rb = (uint32_t)(((bN + nb2 * 16) * PAD + ks * 16 + bKs) * 2);
            ldsm4(bh[nb2], Bh_u + rb);
            ldsm4(bl[nb2], Bl_u + rb);
        }
#pragma unroll
        for (int mi = 0; mi < 2; mi++)
#pragma unroll
            for (int nb = 0; nb < 4; nb++) {
                const uint32_t* bhp = &bh[nb >> 1][(nb & 1) * 2];
                const uint32_t* blp = &bl[nb >> 1][(nb & 1) * 2];
                mma16816(acc[mi][nb], ah[mi], bhp);
                mma16816(acc[mi][nb], ah[mi], blp);
                mma16816(acc[mi][nb], al[mi], bhp);
            }
    }

    // ---- epilogue: bias, store, per-column stats ----
    float* outp = (MODE == 1) ? g_Y1 : g_P;
    float cs[4][2], cq[4][2];
#pragma unroll
    for (int nb = 0; nb < 4; nb++) { cs[nb][0] = cs[nb][1] = 0.f; cq[nb][0] = cq[nb][1] = 0.f; }
    float bse[4][2];
#pragma unroll
    for (int nb = 0; nb < 4; nb++) {
        int c = wn * 32 + nb * 8 + (lane & 3) * 2;
        bse[nb][0] = __ldg(bias + c);
        bse[nb][1] = __ldg(bias + c + 1);
    }
#pragma unroll
    for (int mi = 0; mi < 2; mi++) {
        int r0 = m0 + wm * 32 + mi * 16 + (lane >> 2);
        int r1 = r0 + 8;
        bool v0 = r0 < NN, v1 = r1 < NN;
#pragma unroll
        for (int nb = 0; nb < 4; nb++) {
            int c = wn * 32 + nb * 8 + (lane & 3) * 2;
            float o0 = acc[mi][nb][0] + bse[nb][0];
            float o1 = acc[mi][nb][1] + bse[nb][1];
            float o2 = acc[mi][nb][2] + bse[nb][0];
            float o3 = acc[mi][nb][3] + bse[nb][1];
            if (v0) {
                *(float2*)(outp + (size_t)r0 * HH + c) = make_float2(o0, o1);
                cs[nb][0] += o0; cs[nb][1] += o1;
                cq[nb][0] += o0 * o0; cq[nb][1] += o1 * o1;
            }
            if (v1) {
                *(float2*)(outp + (size_t)r1 * HH + c) = make_float2(o2, o3);
                cs[nb][0] += o2; cs[nb][1] += o3;
                cq[nb][0] += o2 * o2; cq[nb][1] += o3 * o3;
            }
        }
    }
    // reduce across row-groups (lanes with same lane&3)
#pragma unroll
    for (int nb = 0; nb < 4; nb++) {
#pragma unroll
        for (int j = 0; j < 2; j++) {
            float s = cs[nb][j], q = cq[nb][j];
#pragma unroll
            for (int off = 16; off >= 4; off >>= 1) {
                s += __shfl_down_sync(0xffffffffu, s, off);
                q += __shfl_down_sync(0xffffffffu, q, off);
            }
            if (lane < 4) {
                int c = wn * 32 + nb * 8 + lane * 2 + j;
                sS[wm * HH + c] = s;
                sQ[wm * HH + c] = q;
            }
        }
    }
    __syncthreads();
    if (tid < HH) {
        float s = sS[tid] + sS[HH + tid] + sS[2 * HH + tid] + sS[3 * HH + tid];
        float q = sQ[tid] + sQ[HH + tid] + sQ[2 * HH + tid] + sQ[3 * HH + tid];
        float* st = g_stats + ((MODE == 1) ? 0 : 2 * HH);
        atomicAdd(st + tid, s);
        atomicAdd(st + HH + tid, q);
    }
}

__global__ void k_bnstat(int set) {
    int j = threadIdx.x;
    float s  = g_stats[set * 2 * HH + j];
    float sq = g_stats[set * 2 * HH + HH + j];
    float mu = s * (1.f / (float)NN);
    float var = sq * (1.f / (float)NN) - mu * mu;
    g_bn[set * 2 * HH + j] = mu;
    g_bn[set * 2 * HH + HH + j] = rsqrtf(var + 1e-5f);
}

__global__ void k_pool(const int* __restrict__ batch,
                       const float* __restrict__ bg, const float* __restrict__ bb) {
    int idx = blockIdx.x * blockDim.x + threadIdx.x;
    int n = idx >> 5; if (n >= NN) return;
    int c = (idx & 31) << 2;
    float4 y = *(const float4*)(g_P + (size_t)n * HH + c);
    float s0 = __ldg(bg + c + 0) * g_bn[3 * HH + c + 0];
    float s1 = __ldg(bg + c + 1) * g_bn[3 * HH + c + 1];
    float s2 = __ldg(bg + c + 2) * g_bn[3 * HH + c + 2];
    float s3 = __ldg(bg + c + 3) * g_bn[3 * HH + c + 3];
    float4 o;
    o.x = fmaf(s0, y.x - g_bn[2 * HH + c + 0], __ldg(bb + c + 0));
    o.y = fmaf(s1, y.y - g_bn[2 * HH + c + 1], __ldg(bb + c + 1));
    o.z = fmaf(s2, y.z - g_bn[2 * HH + c + 2], __ldg(bb + c + 2));
    o.w = fmaf(s3, y.w - g_bn[2 * HH + c + 3], __ldg(bb + c + 3));
    red_add_v4(g_pool + (size_t)__ldg(batch + n) * HH + c, o);
}

__global__ void k_final(const float* __restrict__ cw1, const float* __restrict__ cb1,
                        const float* __restrict__ cw2, const float* __restrict__ cb2,
                        float* __restrict__ out) {
    __shared__ float p[HH];
    __shared__ float rb[4];
    int j = threadIdx.x;
    p[j] = g_pool[(size_t)blockIdx.x * HH + j];
    __syncthreads();
    float acc = __ldg(cb1 + j);
#pragma unroll 8
    for (int i = 0; i < HH; i++)
        acc = fmaf(p[i], __ldg(cw1 + i * HH + j), acc);
    float v = fmaxf(acc, 0.f) * __ldg(cw2 + j);
#pragma unroll
    for (int off = 16; off > 0; off >>= 1)
        v += __shfl_down_sync(0xffffffffu, v, off);
    if ((j & 31) == 0) rb[j >> 5] = v;
    __syncthreads();
    if (j == 0) out[blockIdx.x] = rb[0] + rb[1] + rb[2] + rb[3] + __ldg(cb2);
}

extern "C" void kernel_launch(void* const* d_in, const int* in_sizes, int n_in,
                              void* d_out, int out_size) {
    const int*   x     = (const int*)d_in[0];
    const int*   ei    = (const int*)d_in[1];
    const int*   ea    = (const int*)d_in[2];
    const int*   batch = (const int*)d_in[3];
    const float* aemb  = (const float*)d_in[4];
    const float* bemb  = (const float*)d_in[5];
    const float* eps   = (const float*)d_in[6];
    const float* w1    = (const float*)d_in[7];
    const float* b1    = (const float*)d_in[8];
    const float* bn1g  = (const float*)d_in[9];
    const float* bn1b  = (const float*)d_in[10];
    const float* w2    = (const float*)d_in[11];
    const float* b2    = (const float*)d_in[12];
    const float* bng   = (const float*)d_in[13];
    const float* bnb   = (const float*)d_in[14];
    const float* cw1   = (const float*)d_in[15];
    const float* cb1   = (const float*)d_in[16];
    const float* cw2   = (const float*)d_in[17];
    const float* cb2   = (const float*)d_in[18];
    float* out = (float*)d_out;
    const int* row = ei;
    const int* col = ei + EE;

    cudaFuncSetAttribute(k_mma<1>, cudaFuncAttributeMaxDynamicSharedMemorySize, GEMM_SMEM);
    cudaFuncSetAttribute(k_mma<2>, cudaFuncAttributeMaxDynamicSharedMemorySize, GEMM_SMEM);

    const int NT = 256;
    const int gridNH = (NN * 32 + NT - 1) / NT;   // 37500
    const int gridEH = (EE * 32 + NT - 1) / NT;   // 75000
    const int gridGEMM = (NN + 127) / 128;        // 2344

    k_init<<<4096, NT>>>();
    k_prepw<<<dim3(16, 10), 256>>>(w1, w2);
    k_atom<<<gridNH, NT>>>(x, aemb);
    k_deg<<<(EE + NT - 1) / NT, NT>>>(row);
    for (int l = 0; l < 5; l++) {
        k_bond<<<gridEH, NT>>>(row, ea, bemb + (size_t)l * 3 * 8 * HH);
        if (l == 0)
            k_hin<1><<<gridNH, NT>>>(nullptr, nullptr);
        else
            k_hin<0><<<gridNH, NT>>>(bng + (l - 1) * HH, bnb + (l - 1) * HH);
        k_aggr<<<gridEH, NT>>>(row, col);
        k_mma<1><<<gridGEMM, 512, GEMM_SMEM>>>(2 * l, b1 + l * HH, eps + l, nullptr, nullptr);
        k_bnstat<<<1, HH>>>(0);
        k_mma<2><<<gridGEMM, 512, GEMM_SMEM>>>(2 * l + 1, b2 + l * HH, nullptr,
                                               bn1g + l * HH, bn1b + l * HH);
        k_bnstat<<<1, HH>>>(1);
    }
    k_pool<<<gridNH, NT>>>(batch, bng + 4 * HH, bnb + 4 * HH);
    k_final<<<GG, HH>>>(cw1, cb1, cw2, cb2, out);
}

// round 6
// speedup vs baseline: 8.5153x; 1.1119x over previous
#include <cuda_runtime.h>
#include <cuda_bf16.h>
#include <cstdint>

#define NN 300000
#define EE 600000
#define HH 128
#define GG 8192

// ---------------- scratch (device globals: allocation-free) ----------------
__device__ float g_P[(size_t)NN * HH];    // prev-layer raw output (atom enc / y2 pre-BN)
__device__ float g_HIN[(size_t)NN * HH];  // h_in
__device__ float g_ACC[(size_t)NN * HH];  // atomic accumulator (kept zeroed)
__device__ float g_Y1[(size_t)NN * HH];   // y1 (pre-BN1 GEMM1 output)
__device__ float g_pool[(size_t)GG * HH];
__device__ float g_stats[4 * HH];         // [sum1, sumsq1, sum2, sumsq2]
__device__ float g_bn[4 * HH];            // [mu1, rstd1, mu2, rstd2]
__device__ __nv_bfloat16 g_Wh[10 * HH * HH];
__device__ __nv_bfloat16 g_Wl[10 * HH * HH];
// CSR by row + packed edge payload (col | cidx<<19)
__device__ int g_cnt[NN];
__device__ int g_cur[NN];
__device__ int g_off[NN + 1];
__device__ unsigned int g_pack[EE];
// precombined bond tables: [5][216][128]
__device__ float g_ctab[5 * 216 * HH];

__device__ __forceinline__ void red_add_v4(float* p, float4 v) {
    asm volatile("red.global.add.v4.f32 [%0], {%1,%2,%3,%4};"
                 :: "l"(p), "f"(v.x), "f"(v.y), "f"(v.z), "f"(v.w) : "memory");
}
__device__ __forceinline__ uint32_t smem_u32(const void* p) {
    uint32_t a;
    asm("{ .reg .u64 t; cvta.to.shared.u64 t, %1; cvt.u32.u64 %0, t; }" : "=r"(a) : "l"(p));
    return a;
}
__device__ __forceinline__ void ldsm4(uint32_t* r, uint32_t addr) {
    asm volatile("ldmatrix.sync.aligned.m8n8.x4.shared.b16 {%0,%1,%2,%3}, [%4];"
                 : "=r"(r[0]), "=r"(r[1]), "=r"(r[2]), "=r"(r[3]) : "r"(addr));
}
__device__ __forceinline__ void mma16816(float* d, const uint32_t* a, const uint32_t* b) {
    asm volatile("mma.sync.aligned.m16n8k16.row.col.f32.bf16.bf16.f32 "
                 "{%0,%1,%2,%3}, {%4,%5,%6,%7}, {%8,%9}, {%0,%1,%2,%3};"
                 : "+f"(d[0]), "+f"(d[1]), "+f"(d[2]), "+f"(d[3])
                 : "r"(a[0]), "r"(a[1]), "r"(a[2]), "r"(a[3]), "r"(b[0]), "r"(b[1]));
}

// ---------------- setup kernels ----------------
__global__ void k_init() {
    size_t stride = (size_t)gridDim.x * blockDim.x;
    size_t i0 = (size_t)blockIdx.x * blockDim.x + threadIdx.x;
    for (size_t i = i0; i < (size_t)NN * HH; i += stride) g_ACC[i] = 0.f;
    for (size_t i = i0; i < (size_t)NN; i += stride) { g_cnt[i] = 0; g_cur[i] = 0; }
    for (size_t i = i0; i < (size_t)GG * HH; i += stride) g_pool[i] = 0.f;
}

__global__ void k_prepw(const float* __restrict__ w1, const float* __restrict__ w2) {
    int l = blockIdx.y;   // 0..9
    const float* W = (l < 5) ? (w1 + (size_t)l * HH * HH) : (w2 + (size_t)(l - 5) * HH * HH);
    int slot = (l < 5) ? (2 * l) : (2 * (l - 5) + 1);
    int q = blockIdx.x * 256 + threadIdx.x;
    int k = q >> 5, n0 = (q & 31) * 4;
    float4 w = *(const float4*)(W + (size_t)k * HH + n0);
    float wv[4] = {w.x, w.y, w.z, w.w};
#pragma unroll
    for (int j = 0; j < 4; j++) {
        __nv_bfloat16 h = __float2bfloat16(wv[j]);
        size_t o = (size_t)slot * HH * HH + (size_t)(n0 + j) * HH + k;
        g_Wh[o] = h;
        g_Wl[o] = __float2bfloat16(wv[j] - __bfloat162float(h));
    }
}

__global__ void k_prepbond(const float* __restrict__ bemb) {
    int c = blockIdx.x;   // 0..215
    int l = blockIdx.y;   // 0..4
    int h = threadIdx.x;  // 0..127
    int a0 = c / 36, a1 = (c / 6) % 6, a2 = c % 6;
    const float* b = bemb + (size_t)l * 3 * 8 * HH;
    g_ctab[((size_t)l * 216 + c) * HH + h] =
        b[(size_t)(0 * 8 + a0) * HH + h] + b[(size_t)(1 * 8 + a1) * HH + h]
        + b[(size_t)(2 * 8 + a2) * HH + h];
}

__global__ void k_atom(const int* __restrict__ x, const float* __restrict__ aemb) {
    int idx = blockIdx.x * blockDim.x + threadIdx.x;
    int n = idx >> 5; if (n >= NN) return;
    int c = (idx & 31) << 2;
    float4 acc = make_float4(0.f, 0.f, 0.f, 0.f);
#pragma unroll
    for (int f = 0; f < 9; f++) {
        int xi = __ldg(x + n * 9 + f);
        float4 e = *(const float4*)(aemb + ((size_t)(f * 128 + xi) * HH + c));
        acc.x += e.x; acc.y += e.y; acc.z += e.z; acc.w += e.w;
    }
    *(float4*)(g_P + (size_t)n * HH + c) = acc;
}

__global__ void k_cnt(const int* __restrict__ row) {
    int e = blockIdx.x * blockDim.x + threadIdx.x;
    if (e < EE) atomicAdd(&g_cnt[__ldg(row + e)], 1);
}

// single-block exclusive scan of g_cnt -> g_off
__global__ void k_scan() {
    __shared__ int bs[1024];
    const int t = threadIdx.x;
    const int C = (NN + 1023) / 1024;   // 293
    int base = t * C;
    int s = 0;
    for (int i = 0; i < C; i++) {
        int idx = base + i;
        if (idx < NN) s += g_cnt[idx];
    }
    bs[t] = s;
    __syncthreads();
    for (int off = 1; off < 1024; off <<= 1) {
        int u = (t >= off) ? bs[t - off] : 0;
        __syncthreads();
        bs[t] += u;
        __syncthreads();
    }
    int run = bs[t] - s;   // exclusive prefix of this chunk
    for (int i = 0; i < C; i++) {
        int idx = base + i;
        if (idx < NN) { g_off[idx] = run; run += g_cnt[idx]; }
    }
    if (t == 1023) g_off[NN] = EE;
}

__global__ void k_fill(const int* __restrict__ row, const int* __restrict__ col,
                       const int* __restrict__ eattr) {
    int e = blockIdx.x * blockDim.x + threadIdx.x;
    if (e >= EE) return;
    int r = __ldg(row + e);
    int a0 = __ldg(eattr + e * 3 + 0);
    int a1 = __ldg(eattr + e * 3 + 1);
    int a2 = __ldg(eattr + e * 3 + 2);
    unsigned int cidx = (unsigned int)(a0 * 36 + a1 * 6 + a2);
    int pos = g_off[r] + atomicAdd(&g_cur[r], 1);
    g_pack[pos] = (unsigned int)__ldg(col + e) | (cidx << 19);
}

// ---------------- fused node kernel (bond + hin + aggr scatter) ----------------
// warp per node: besum over out-edges (CSR, no atomics), hin = act(P)+besum*inv,
// write HIN, scatter hin to ACC[col] (RED). Also zeroes g_stats.
// FIRST=1: act = identity. FIRST=0: act = relu(bn2(P)) with BN2 stats (slots 2HH/3HH).
template<int FIRST>
__global__ void __launch_bounds__(256)
k_node(int layer, const float* __restrict__ bg, const float* __restrict__ bb) {
    __shared__ float s_sc[HH], s_sh[HH];
    const int tid = threadIdx.x;
    int gidx = blockIdx.x * 256 + tid;
    if (gidx < 4 * HH) g_stats[gidx] = 0.f;
    if (!FIRST) {
        if (tid < HH) {
            float s = __ldg(bg + tid) * g_bn[3 * HH + tid];   // gamma * rstd2  (FIXED)
            s_sc[tid] = s;
            s_sh[tid] = __ldg(bb + tid) - s * g_bn[2 * HH + tid];  // beta - s*mu2 (FIXED)
        }
        __syncthreads();
    }
    const int n = blockIdx.x * 8 + (tid >> 5);
    if (n >= NN) return;
    const int c4 = (tid & 31) << 2;
    const float* ctab = g_ctab + (size_t)layer * 216 * HH;
    const int e0 = __ldg(&g_off[n]), e1 = __ldg(&g_off[n + 1]);
    const float inv = 1.f / ((float)(e1 - e0) + 1.f);

    float4 bsum = make_float4(0.f, 0.f, 0.f, 0.f);
    for (int e = e0; e < e1; e++) {
        unsigned int pk = __ldg(&g_pack[e]);
        const float4 t = *(const float4*)(ctab + (size_t)(pk >> 19) * HH + c4);
        bsum.x += t.x; bsum.y += t.y; bsum.z += t.z; bsum.w += t.w;
    }
    float4 p = *(const float4*)(g_P + (size_t)n * HH + c4);
    if (!FIRST) {
        p.x = fmaxf(fmaf(s_sc[c4 + 0], p.x, s_sh[c4 + 0]), 0.f);
        p.y = fmaxf(fmaf(s_sc[c4 + 1], p.y, s_sh[c4 + 1]), 0.f);
        p.z = fmaxf(fmaf(s_sc[c4 + 2], p.z, s_sh[c4 + 2]), 0.f);
        p.w = fmaxf(fmaf(s_sc[c4 + 3], p.w, s_sh[c4 + 3]), 0.f);
    }
    float4 h;
    h.x = fmaf(bsum.x, inv, p.x);
    h.y = fmaf(bsum.y, inv, p.y);
    h.z = fmaf(bsum.z, inv, p.z);
    h.w = fmaf(bsum.w, inv, p.w);
    *(float4*)(g_HIN + (size_t)n * HH + c4) = h;

    for (int e = e0; e < e1; e++) {
        unsigned int pk = __ldg(&g_pack[e]);
        red_add_v4(g_ACC + (size_t)(pk & 0x7FFFFu) * HH + c4, h);
    }
}

// ---------------- HMMA bf16-split GEMM (unchanged from R4) ----------------
#define PAD 136
#define GEMM_SMEM (4 * 34816 + 4096)

template<int MODE>
__global__ void __launch_bounds__(512, 1)
k_mma(int wslot, const float* __restrict__ bias,
      const float* __restrict__ epsp,
      const float* __restrict__ bg, const float* __restrict__ bb) {
    extern __shared__ char dsm[];
    __shared__ float s_sc[HH], s_sh[HH];

    const uint32_t su = smem_u32(dsm);
    const uint32_t Ah_u = su, Al_u = su + 34816;
    const uint32_t Bh_u = su + 69632, Bl_u = su + 104448;
    __nv_bfloat16* Ah = (__nv_bfloat16*)dsm;
    __nv_bfloat16* Al = (__nv_bfloat16*)(dsm + 34816);
    __nv_bfloat16* Bh = (__nv_bfloat16*)(dsm + 69632);
    __nv_bfloat16* Bl = (__nv_bfloat16*)(dsm + 104448);
    float* sS = (float*)(dsm + 139264);
    float* sQ = (float*)(dsm + 141312);

    const int tid = threadIdx.x;
    const int wid = tid >> 5, lane = tid & 31;
    const int wm = wid & 3, wn = wid >> 2;
    const int m0 = blockIdx.x * 128;

    if (MODE == 2 && tid < HH) {
        float s = __ldg(bg + tid) * g_bn[HH + tid];
        s_sc[tid] = s;
        s_sh[tid] = __ldg(bb + tid) - s * g_bn[tid];
    }
    const float epsl = (MODE == 1) ? (1.f + __ldg(epsp)) : 0.f;
    if (MODE == 2) __syncthreads();

    const __nv_bfloat16* wh = g_Wh + (size_t)wslot * HH * HH;
    const __nv_bfloat16* wl = g_Wl + (size_t)wslot * HH * HH;
#pragma unroll
    for (int it = 0; it < 4; it++) {
        int q = it * 512 + tid;
        int n = q >> 4, k0 = (q & 15) * 8;
        *(uint4*)(Bh + n * PAD + k0) = *(const uint4*)(wh + n * HH + k0);
        *(uint4*)(Bl + n * PAD + k0) = *(const uint4*)(wl + n * HH + k0);
    }
#pragma unroll
    for (int it = 0; it < 8; it++) {
        int q = it * 512 + tid;
        int r = q >> 5, c0 = (q & 31) * 4;
        int grow = m0 + r;
        float4 v = make_float4(0.f, 0.f, 0.f, 0.f);
        if (grow < NN) {
            if (MODE == 1) {
                float4 cv = *(const float4*)(g_HIN + (size_t)grow * HH + c0);
                float4 bv = *(const float4*)(g_ACC + (size_t)grow * HH + c0);
                v.x = fmaf(epsl, cv.x, bv.x);
                v.y = fmaf(epsl, cv.y, bv.y);
                v.z = fmaf(epsl, cv.z, bv.z);
                v.w = fmaf(epsl, cv.w, bv.w);
                *(float4*)(g_ACC + (size_t)grow * HH + c0) = make_float4(0.f, 0.f, 0.f, 0.f);
            } else {
                float4 y = *(const float4*)(g_Y1 + (size_t)grow * HH + c0);
                v.x = fmaxf(fmaf(s_sc[c0 + 0], y.x, s_sh[c0 + 0]), 0.f);
                v.y = fmaxf(fmaf(s_sc[c0 + 1], y.y, s_sh[c0 + 1]), 0.f);
                v.z = fmaxf(fmaf(s_sc[c0 + 2], y.z, s_sh[c0 + 2]), 0.f);
                v.w = fmaxf(fmaf(s_sc[c0 + 3], y.w, s_sh[c0 + 3]), 0.f);
            }
        }
        float fv[4] = {v.x, v.y, v.z, v.w};
        __nv_bfloat16 hb[4], lb[4];
#pragma unroll
        for (int j = 0; j < 4; j++) {
            hb[j] = __float2bfloat16(fv[j]);
            lb[j] = __float2bfloat16(fv[j] - __bfloat162float(hb[j]));
        }
        *(uint2*)(Ah + r * PAD + c0) = *(uint2*)hb;
        *(uint2*)(Al + r * PAD + c0) = *(uint2*)lb;
    }
    __syncthreads();

    float acc[2][4][4];
#pragma unroll
    for (int mi = 0; mi < 2; mi++)
#pragma unroll
        for (int nb = 0; nb < 4; nb++)
#pragma unroll
            for (int j = 0; j < 4; j++) acc[mi][nb][j] = 0.f;

    const int aRow = wm * 32 + (lane & 15);
    const int aKs = (lane >> 4) * 8;
    const int bN = wn * 32 + (lane >> 4) * 8 + (lane & 7);
    const int bKs = ((lane >> 3) & 1) * 8;

#pragma unroll
    for (int ks = 0; ks < 8; ks++) {
        uint32_t ah[2][4], al[2][4], bh[2][4], bl[2][4];
#pragma unroll
        for (int mi = 0; mi < 2; mi++) {
            uint32_t ra = (uint32_t)(((aRow + mi * 16) * PAD + ks * 16 + aKs) * 2);
            ldsm4(ah[mi], Ah_u + ra);
            ldsm4(al[mi], Al_u + ra);
        }
#pragma unroll
        for (int nb2 = 0; nb2 < 2; nb2++) {
            uint32_t rb = (uint32_t)(((bN + nb2 * 16) * PAD + ks * 16 + bKs) * 2);
            ldsm4(bh[nb2], Bh_u + rb);
            ldsm4(bl[nb2], Bl_u + rb);
        }
#pragma unroll
        for (int mi = 0; mi < 2; mi++)
#pragma unroll
            for (int nb = 0; nb < 4; nb++) {
                const uint32_t* bhp = &bh[nb >> 1][(nb & 1) * 2];
                const uint32_t* blp = &bl[nb >> 1][(nb & 1) * 2];
                mma16816(acc[mi][nb], ah[mi], bhp);
                mma16816(acc[mi][nb], ah[mi], blp);
                mma16816(acc[mi][nb], al[mi], bhp);
            }
    }

    float* outp = (MODE == 1) ? g_Y1 : g_P;
    float cs[4][2], cq[4][2];
#pragma unroll
    for (int nb = 0; nb < 4; nb++) { cs[nb][0] = cs[nb][1] = 0.f; cq[nb][0] = cq[nb][1] = 0.f; }
    float bse[4][2];
#pragma unroll
    for (int nb = 0; nb < 4; nb++) {
        int c = wn * 32 + nb * 8 + (lane & 3) * 2;
        bse[nb][0] = __ldg(bias + c);
        bse[nb][1] = __ldg(bias + c + 1);
    }
#pragma unroll
    for (int mi = 0; mi < 2; mi++) {
        int r0 = m0 + wm * 32 + mi * 16 + (lane >> 2);
        int r1 = r0 + 8;
        bool v0 = r0 < NN, v1 = r1 < NN;
#pragma unroll
        for (int nb = 0; nb < 4; nb++) {
            int c = wn * 32 + nb * 8 + (lane & 3) * 2;
            float o0 = acc[mi][nb][0] + bse[nb][0];
            float o1 = acc[mi][nb][1] + bse[nb][1];
            float o2 = acc[mi][nb][2] + bse[nb][0];
            float o3 = acc[mi][nb][3] + bse[nb][1];
            if (v0) {
                *(float2*)(outp + (size_t)r0 * HH + c) = make_float2(o0, o1);
                cs[nb][0] += o0; cs[nb][1] += o1;
                cq[nb][0] += o0 * o0; cq[nb][1] += o1 * o1;
            }
            if (v1) {
                *(float2*)(outp + (size_t)r1 * HH + c) = make_float2(o2, o3);
                cs[nb][0] += o2; cs[nb][1] += o3;
                cq[nb][0] += o2 * o2; cq[nb][1] += o3 * o3;
            }
        }
    }
#pragma unroll
    for (int nb = 0; nb < 4; nb++) {
#pragma unroll
        for (int j = 0; j < 2; j++) {
            float s = cs[nb][j], q = cq[nb][j];
#pragma unroll
            for (int off = 16; off >= 4; off >>= 1) {
                s += __shfl_down_sync(0xffffffffu, s, off);
                q += __shfl_down_sync(0xffffffffu, q, off);
            }
            if (lane < 4) {
                int c = wn * 32 + nb * 8 + lane * 2 + j;
                sS[wm * HH + c] = s;
                sQ[wm * HH + c] = q;
            }
        }
    }
    __syncthreads();
    if (tid < HH) {
        float s = sS[tid] + sS[HH + tid] + sS[2 * HH + tid] + sS[3 * HH + tid];
        float q = sQ[tid] + sQ[HH + tid] + sQ[2 * HH + tid] + sQ[3 * HH + tid];
        float* st = g_stats + ((MODE == 1) ? 0 : 2 * HH);
        atomicAdd(st + tid, s);
        atomicAdd(st + HH + tid, q);
    }
}

__global__ void k_bnstat(int set) {
    int j = threadIdx.x;
    float s  = g_stats[set * 2 * HH + j];
    float sq = g_stats[set * 2 * HH + HH + j];
    float mu = s * (1.f / (float)NN);
    float var = sq * (1.f / (float)NN) - mu * mu;
    g_bn[set * 2 * HH + j] = mu;
    g_bn[set * 2 * HH + HH + j] = rsqrtf(var + 1e-5f);
}

__global__ void k_pool(const int* __restrict__ batch,
                       const float* __restrict__ bg, const float* __restrict__ bb) {
    int idx = blockIdx.x * blockDim.x + threadIdx.x;
    int n = idx >> 5; if (n >= NN) return;
    int c = (idx & 31) << 2;
    float4 y = *(const float4*)(g_P + (size_t)n * HH + c);
    float s0 = __ldg(bg + c + 0) * g_bn[3 * HH + c + 0];
    float s1 = __ldg(bg + c + 1) * g_bn[3 * HH + c + 1];
    float s2 = __ldg(bg + c + 2) * g_bn[3 * HH + c + 2];
    float s3 = __ldg(bg + c + 3) * g_bn[3 * HH + c + 3];
    float4 o;
    o.x = fmaf(s0, y.x - g_bn[2 * HH + c + 0], __ldg(bb + c + 0));
    o.y = fmaf(s1, y.y - g_bn[2 * HH + c + 1], __ldg(bb + c + 1));
    o.z = fmaf(s2, y.z - g_bn[2 * HH + c + 2], __ldg(bb + c + 2));
    o.w = fmaf(s3, y.w - g_bn[2 * HH + c + 3], __ldg(bb + c + 3));
    red_add_v4(g_pool + (size_t)__ldg(batch + n) * HH + c, o);
}

__global__ void k_final(const float* __restrict__ cw1, const float* __restrict__ cb1,
                        const float* __restrict__ cw2, const float* __restrict__ cb2,
                        float* __restrict__ out) {
    __shared__ float p[HH];
    __shared__ float rb[4];
    int j = threadIdx.x;
    p[j] = g_pool[(size_t)blockIdx.x * HH + j];
    __syncthreads();
    float acc = __ldg(cb1 + j);
#pragma unroll 8
    for (int i = 0; i < HH; i++)
        acc = fmaf(p[i], __ldg(cw1 + i * HH + j), acc);
    float v = fmaxf(acc, 0.f) * __ldg(cw2 + j);
#pragma unroll
    for (int off = 16; off > 0; off >>= 1)
        v += __shfl_down_sync(0xffffffffu, v, off);
    if ((j & 31) == 0) rb[j >> 5] = v;
    __syncthreads();
    if (j == 0) out[blockIdx.x] = rb[0] + rb[1] + rb[2] + rb[3] + __ldg(cb2);
}

extern "C" void kernel_launch(void* const* d_in, const int* in_sizes, int n_in,
                              void* d_out, int out_size) {
    const int*   x     = (const int*)d_in[0];
    const int*   ei    = (const int*)d_in[1];
    const int*   ea    = (const int*)d_in[2];
    const int*   batch = (const int*)d_in[3];
    const float* aemb  = (const float*)d_in[4];
    const float* bemb  = (const float*)d_in[5];
    const float* eps   = (const float*)d_in[6];
    const float* w1    = (const float*)d_in[7];
    const float* b1    = (const float*)d_in[8];
    const float* bn1g  = (const float*)d_in[9];
    const float* bn1b  = (const float*)d_in[10];
    const float* w2    = (const float*)d_in[11];
    const float* b2    = (const float*)d_in[12];
    const float* bng   = (const float*)d_in[13];
    const float* bnb   = (const float*)d_in[14];
    const float* cw1   = (const float*)d_in[15];
    const float* cb1   = (const float*)d_in[16];
    const float* cw2   = (const float*)d_in[17];
    const float* cb2   = (const float*)d_in[18];
    float* out = (float*)d_out;
    const int* row = ei;
    const int* col = ei + EE;

    cudaFuncSetAttribute(k_mma<1>, cudaFuncAttributeMaxDynamicSharedMemorySize, GEMM_SMEM);
    cudaFuncSetAttribute(k_mma<2>, cudaFuncAttributeMaxDynamicSharedMemorySize, GEMM_SMEM);

    const int NT = 256;
    const int gridNH = (NN * 32 + NT - 1) / NT;   // 37500
    const int gridE  = (EE + NT - 1) / NT;
    const int gridGEMM = (NN + 127) / 128;        // 2344
    const int gridNode = (NN + 7) / 8;            // 37500

    k_init<<<4096, NT>>>();
    k_prepw<<<dim3(16, 10), 256>>>(w1, w2);
    k_prepbond<<<dim3(216, 5), HH>>>(bemb);
    k_atom<<<gridNH, NT>>>(x, aemb);
    k_cnt<<<gridE, NT>>>(row);
    k_scan<<<1, 1024>>>();
    k_fill<<<gridE, NT>>>(row, col, ea);
    for (int l = 0; l < 5; l++) {
        if (l == 0)
            k_node<1><<<gridNode, NT>>>(0, nullptr, nullptr);
        else
            k_node<0><<<gridNode, NT>>>(l, bng + (l - 1) * HH, bnb + (l - 1) * HH);
        k_mma<1><<<gridGEMM, 512, GEMM_SMEM>>>(2 * l, b1 + l * HH, eps + l, nullptr, nullptr);
        k_bnstat<<<1, HH>>>(0);
        k_mma<2><<<gridGEMM, 512, GEMM_SMEM>>>(2 * l + 1, b2 + l * HH, nullptr,
                                               bn1g + l * HH, bn1b + l * HH);
        k_bnstat<<<1, HH>>>(1);
    }
    k_pool<<<gridNH, NT>>>(batch, bng + 4 * HH, bnb + 4 * HH);
    k_final<<<GG, HH>>>(cw1, cb1, cw2, cb2, out);
}

// round 7
// speedup vs baseline: 10.5934x; 1.2441x over previous
#include <cuda_runtime.h>
#include <cuda_bf16.h>
#include <cstdint>

#define NN 300000
#define EE 600000
#define HH 128
#define GG 8192

// ---------------- scratch (device globals: allocation-free) ----------------
__device__ float g_P[(size_t)NN * HH];    // prev-layer raw output (atom enc / y2 pre-BN)
__device__ float g_HIN[(size_t)NN * HH];  // h_in
__device__ float g_Y1[(size_t)NN * HH];   // y1 (pre-BN1 GEMM1 output)
__device__ float g_pool[(size_t)GG * HH];
__device__ float g_stats[4 * HH];         // [sum1, sumsq1, sum2, sumsq2]
__device__ float g_bn[4 * HH];            // [mu1, rstd1, mu2, rstd2]
__device__ __nv_bfloat16 g_Wh[10 * HH * HH];
__device__ __nv_bfloat16 g_Wl[10 * HH * HH];
// CSR by row (payload cidx) for bond sums; CSC by col (payload row) for aggr gather
__device__ int g_cnt[NN],  g_cur[NN],  g_off[NN + 1];
__device__ int g_cnt2[NN], g_cur2[NN], g_off2[NN + 1];
__device__ unsigned int g_pack[EE];    // cidx (bond table index)
__device__ int g_pack2[EE];            // src row
// precombined bond tables: [5][216][128]
__device__ float g_ctab[5 * 216 * HH];

__device__ __forceinline__ void red_add_v4(float* p, float4 v) {
    asm volatile("red.global.add.v4.f32 [%0], {%1,%2,%3,%4};"
                 :: "l"(p), "f"(v.x), "f"(v.y), "f"(v.z), "f"(v.w) : "memory");
}
__device__ __forceinline__ uint32_t smem_u32(const void* p) {
    uint32_t a;
    asm("{ .reg .u64 t; cvta.to.shared.u64 t, %1; cvt.u32.u64 %0, t; }" : "=r"(a) : "l"(p));
    return a;
}
__device__ __forceinline__ void ldsm4(uint32_t* r, uint32_t addr) {
    asm volatile("ldmatrix.sync.aligned.m8n8.x4.shared.b16 {%0,%1,%2,%3}, [%4];"
                 : "=r"(r[0]), "=r"(r[1]), "=r"(r[2]), "=r"(r[3]) : "r"(addr));
}
__device__ __forceinline__ void mma16816(float* d, const uint32_t* a, const uint32_t* b) {
    asm volatile("mma.sync.aligned.m16n8k16.row.col.f32.bf16.bf16.f32 "
                 "{%0,%1,%2,%3}, {%4,%5,%6,%7}, {%8,%9}, {%0,%1,%2,%3};"
                 : "+f"(d[0]), "+f"(d[1]), "+f"(d[2]), "+f"(d[3])
                 : "r"(a[0]), "r"(a[1]), "r"(a[2]), "r"(a[3]), "r"(b[0]), "r"(b[1]));
}

// ---------------- setup kernels ----------------
__global__ void k_init() {
    size_t stride = (size_t)gridDim.x * blockDim.x;
    size_t i0 = (size_t)blockIdx.x * blockDim.x + threadIdx.x;
    for (size_t i = i0; i < (size_t)NN; i += stride) {
        g_cnt[i] = 0; g_cur[i] = 0; g_cnt2[i] = 0; g_cur2[i] = 0;
    }
    for (size_t i = i0; i < (size_t)GG * HH; i += stride) g_pool[i] = 0.f;
}

__global__ void k_prepw(const float* __restrict__ w1, const float* __restrict__ w2) {
    int l = blockIdx.y;   // 0..9
    const float* W = (l < 5) ? (w1 + (size_t)l * HH * HH) : (w2 + (size_t)(l - 5) * HH * HH);
    int slot = (l < 5) ? (2 * l) : (2 * (l - 5) + 1);
    int q = blockIdx.x * 256 + threadIdx.x;
    int k = q >> 5, n0 = (q & 31) * 4;
    float4 w = *(const float4*)(W + (size_t)k * HH + n0);
    float wv[4] = {w.x, w.y, w.z, w.w};
#pragma unroll
    for (int j = 0; j < 4; j++) {
        __nv_bfloat16 h = __float2bfloat16(wv[j]);
        size_t o = (size_t)slot * HH * HH + (size_t)(n0 + j) * HH + k;
        g_Wh[o] = h;
        g_Wl[o] = __float2bfloat16(wv[j] - __bfloat162float(h));
    }
}

__global__ void k_prepbond(const float* __restrict__ bemb) {
    int c = blockIdx.x;   // 0..215
    int l = blockIdx.y;   // 0..4
    int h = threadIdx.x;  // 0..127
    int a0 = c / 36, a1 = (c / 6) % 6, a2 = c % 6;
    const float* b = bemb + (size_t)l * 3 * 8 * HH;
    g_ctab[((size_t)l * 216 + c) * HH + h] =
        b[(size_t)(0 * 8 + a0) * HH + h] + b[(size_t)(1 * 8 + a1) * HH + h]
        + b[(size_t)(2 * 8 + a2) * HH + h];
}

__global__ void k_atom(const int* __restrict__ x, const float* __restrict__ aemb) {
    int idx = blockIdx.x * blockDim.x + threadIdx.x;
    int n = idx >> 5; if (n >= NN) return;
    int c = (idx & 31) << 2;
    float4 acc = make_float4(0.f, 0.f, 0.f, 0.f);
#pragma unroll
    for (int f = 0; f < 9; f++) {
        int xi = __ldg(x + n * 9 + f);
        float4 e = *(const float4*)(aemb + ((size_t)(f * 128 + xi) * HH + c));
        acc.x += e.x; acc.y += e.y; acc.z += e.z; acc.w += e.w;
    }
    *(float4*)(g_P + (size_t)n * HH + c) = acc;
}

__global__ void k_cnt(const int* __restrict__ row, const int* __restrict__ col) {
    int e = blockIdx.x * blockDim.x + threadIdx.x;
    if (e < EE) {
        atomicAdd(&g_cnt[__ldg(row + e)], 1);
        atomicAdd(&g_cnt2[__ldg(col + e)], 1);
    }
}

// exclusive scan: block 0 -> (cnt,off), block 1 -> (cnt2,off2)
__global__ void k_scan() {
    __shared__ int bs[1024];
    const int* cnt = (blockIdx.x == 0) ? g_cnt : g_cnt2;
    int* off = (blockIdx.x == 0) ? g_off : g_off2;
    const int t = threadIdx.x;
    const int C = (NN + 1023) / 1024;   // 293
    int base = t * C;
    int s = 0;
    for (int i = 0; i < C; i++) {
        int idx = base + i;
        if (idx < NN) s += cnt[idx];
    }
    bs[t] = s;
    __syncthreads();
    for (int o = 1; o < 1024; o <<= 1) {
        int u = (t >= o) ? bs[t - o] : 0;
        __syncthreads();
        bs[t] += u;
        __syncthreads();
    }
    int run = bs[t] - s;
    for (int i = 0; i < C; i++) {
        int idx = base + i;
        if (idx < NN) { off[idx] = run; run += cnt[idx]; }
    }
    if (t == 1023) off[NN] = EE;
}

__global__ void k_fill(const int* __restrict__ row, const int* __restrict__ col,
                       const int* __restrict__ eattr) {
    int e = blockIdx.x * blockDim.x + threadIdx.x;
    if (e >= EE) return;
    int r = __ldg(row + e);
    int c = __ldg(col + e);
    int a0 = __ldg(eattr + e * 3 + 0);
    int a1 = __ldg(eattr + e * 3 + 1);
    int a2 = __ldg(eattr + e * 3 + 2);
    int pos = g_off[r] + atomicAdd(&g_cur[r], 1);
    g_pack[pos] = (unsigned int)(a0 * 36 + a1 * 6 + a2);
    int pos2 = g_off2[c] + atomicAdd(&g_cur2[c], 1);
    g_pack2[pos2] = r;
}

// ---------------- node kernel (bond sum + BN2 + hin) ----------------
// warp per node; no atomics, no scatter. Also zeroes g_stats.
template<int FIRST>
__global__ void __launch_bounds__(256)
k_node(int layer, const float* __restrict__ bg, const float* __restrict__ bb) {
    __shared__ float s_sc[HH], s_sh[HH];
    const int tid = threadIdx.x;
    int gidx = blockIdx.x * 256 + tid;
    if (gidx < 4 * HH) g_stats[gidx] = 0.f;
    if (!FIRST) {
        if (tid < HH) {
            float s = __ldg(bg + tid) * g_bn[3 * HH + tid];
            s_sc[tid] = s;
            s_sh[tid] = __ldg(bb + tid) - s * g_bn[2 * HH + tid];
        }
        __syncthreads();
    }
    const int n = blockIdx.x * 8 + (tid >> 5);
    if (n >= NN) return;
    const int c4 = (tid & 31) << 2;
    const float* ctab = g_ctab + (size_t)layer * 216 * HH;
    const int e0 = __ldg(&g_off[n]), e1 = __ldg(&g_off[n + 1]);
    const float inv = 1.f / ((float)(e1 - e0) + 1.f);

    float4 bsum = make_float4(0.f, 0.f, 0.f, 0.f);
    for (int e = e0; e < e1; e++) {
        unsigned int ci = __ldg(&g_pack[e]);
        const float4 t = *(const float4*)(ctab + (size_t)ci * HH + c4);
        bsum.x += t.x; bsum.y += t.y; bsum.z += t.z; bsum.w += t.w;
    }
    float4 p = *(const float4*)(g_P + (size_t)n * HH + c4);
    if (!FIRST) {
        p.x = fmaxf(fmaf(s_sc[c4 + 0], p.x, s_sh[c4 + 0]), 0.f);
        p.y = fmaxf(fmaf(s_sc[c4 + 1], p.y, s_sh[c4 + 1]), 0.f);
        p.z = fmaxf(fmaf(s_sc[c4 + 2], p.z, s_sh[c4 + 2]), 0.f);
        p.w = fmaxf(fmaf(s_sc[c4 + 3], p.w, s_sh[c4 + 3]), 0.f);
    }
    float4 h;
    h.x = fmaf(bsum.x, inv, p.x);
    h.y = fmaf(bsum.y, inv, p.y);
    h.z = fmaf(bsum.z, inv, p.z);
    h.w = fmaf(bsum.w, inv, p.w);
    *(float4*)(g_HIN + (size_t)n * HH + c4) = h;
}

// ---------------- HMMA bf16-split GEMM, M-tile 64, 2 CTAs/SM ----------------
// MODE 1: A = (1+eps)*HIN[n] + sum_{CSC} HIN[src]  (fused gather), out -> Y1, stats 0
// MODE 2: A = relu(bn1(Y1)),                                      out -> P,  stats 1
// smem: Ah(17408) Al(17408) Bh(34816) Bl(34816) sS(1024) sQ(1024) = 106496
#define PAD 136
#define GEMM_SMEM 106496

template<int MODE>
__global__ void __launch_bounds__(256, 2)
k_mma(int wslot, const float* __restrict__ bias,
      const float* __restrict__ epsp,
      const float* __restrict__ bg, const float* __restrict__ bb) {
    extern __shared__ char dsm[];
    __shared__ float s_sc[HH], s_sh[HH];

    const uint32_t su = smem_u32(dsm);
    const uint32_t Ah_u = su, Al_u = su + 17408;
    const uint32_t Bh_u = su + 34816, Bl_u = su + 69632;
    __nv_bfloat16* Ah = (__nv_bfloat16*)dsm;
    __nv_bfloat16* Al = (__nv_bfloat16*)(dsm + 17408);
    __nv_bfloat16* Bh = (__nv_bfloat16*)(dsm + 34816);
    __nv_bfloat16* Bl = (__nv_bfloat16*)(dsm + 69632);
    float* sS = (float*)(dsm + 104448);   // [2][128]
    float* sQ = (float*)(dsm + 105472);   // [2][128]

    const int tid = threadIdx.x;
    const int wid = tid >> 5, lane = tid & 31;
    const int wm = wid & 1, wn = wid >> 1;
    const int m0 = blockIdx.x * 64;

    if (MODE == 2 && tid < HH) {
        float s = __ldg(bg + tid) * g_bn[HH + tid];
        s_sc[tid] = s;
        s_sh[tid] = __ldg(bb + tid) - s * g_bn[tid];
    }
    const float epsl = (MODE == 1) ? (1.f + __ldg(epsp)) : 0.f;
    if (MODE == 2) __syncthreads();

    // ---- W [n][k] hi/lo -> smem (coalesced 16B) ----
    const __nv_bfloat16* wh = g_Wh + (size_t)wslot * HH * HH;
    const __nv_bfloat16* wl = g_Wl + (size_t)wslot * HH * HH;
#pragma unroll
    for (int it = 0; it < 8; it++) {
        int q = it * 256 + tid;
        int n = q >> 4, k0 = (q & 15) * 8;
        *(uint4*)(Bh + n * PAD + k0) = *(const uint4*)(wh + n * HH + k0);
        *(uint4*)(Bl + n * PAD + k0) = *(const uint4*)(wl + n * HH + k0);
    }
    // ---- A: load + transform + split (warp-per-row; MODE1 fuses CSC gather) ----
#pragma unroll
    for (int it = 0; it < 8; it++) {
        int q = it * 256 + tid;
        int r = q >> 5, c0 = (q & 31) * 4;   // whole warp shares r
        int grow = m0 + r;
        float4 v = make_float4(0.f, 0.f, 0.f, 0.f);
        if (grow < NN) {
            if (MODE == 1) {
                float4 hv = *(const float4*)(g_HIN + (size_t)grow * HH + c0);
                v.x = epsl * hv.x; v.y = epsl * hv.y;
                v.z = epsl * hv.z; v.w = epsl * hv.w;
                int e0 = __ldg(&g_off2[grow]), e1 = __ldg(&g_off2[grow + 1]);
                for (int e = e0; e < e1; e++) {
                    int src = __ldg(&g_pack2[e]);
                    float4 s = *(const float4*)(g_HIN + (size_t)src * HH + c0);
                    v.x += s.x; v.y += s.y; v.z += s.z; v.w += s.w;
                }
            } else {
                float4 y = *(const float4*)(g_Y1 + (size_t)grow * HH + c0);
                v.x = fmaxf(fmaf(s_sc[c0 + 0], y.x, s_sh[c0 + 0]), 0.f);
                v.y = fmaxf(fmaf(s_sc[c0 + 1], y.y, s_sh[c0 + 1]), 0.f);
                v.z = fmaxf(fmaf(s_sc[c0 + 2], y.z, s_sh[c0 + 2]), 0.f);
                v.w = fmaxf(fmaf(s_sc[c0 + 3], y.w, s_sh[c0 + 3]), 0.f);
            }
        }
        float fv[4] = {v.x, v.y, v.z, v.w};
        __nv_bfloat16 hb[4], lb[4];
#pragma unroll
        for (int j = 0; j < 4; j++) {
            hb[j] = __float2bfloat16(fv[j]);
            lb[j] = __float2bfloat16(fv[j] - __bfloat162float(hb[j]));
        }
        *(uint2*)(Ah + r * PAD + c0) = *(uint2*)hb;
        *(uint2*)(Al + r * PAD + c0) = *(uint2*)lb;
    }
    __syncthreads();

    // ---- HMMA mainloop: K=128 in 8 steps of 16 ----
    float acc[2][4][4];
#pragma unroll
    for (int mi = 0; mi < 2; mi++)
#pragma unroll
        for (int nb = 0; nb < 4; nb++)
#pragma unroll
            for (int j = 0; j < 4; j++) acc[mi][nb][j] = 0.f;

    const int aRow = wm * 32 + (lane & 15);
    const int aKs = (lane >> 4) * 8;
    const int bN = wn * 32 + (lane >> 4) * 8 + (lane & 7);
    const int bKs = ((lane >> 3) & 1) * 8;

#pragma unroll
    for (int ks = 0; ks < 8; ks++) {
        uint32_t ah[2][4], al[2][4], bh[2][4], bl[2][4];
#pragma unroll
        for (int mi = 0; mi < 2; mi++) {
            uint32_t ra = (uint32_t)(((aRow + mi * 16) * PAD + ks * 16 + aKs) * 2);
            ldsm4(ah[mi], Ah_u + ra);
            ldsm4(al[mi], Al_u + ra);
        }
#pragma unroll
        for (int nb2 = 0; nb2 < 2; nb2++) {
            uint32_t rb = (uint32_t)(((bN + nb2 * 16) * PAD + ks * 16 + bKs) * 2);
            ldsm4(bh[nb2], Bh_u + rb);
            ldsm4(bl[nb2], Bl_u + rb);
        }
#pragma unroll
        for (int mi = 0; mi < 2; mi++)
#pragma unroll
            for (int nb = 0; nb < 4; nb++) {
                const uint32_t* bhp = &bh[nb >> 1][(nb & 1) * 2];
                const uint32_t* blp = &bl[nb >> 1][(nb & 1) * 2];
                mma16816(acc[mi][nb], ah[mi], bhp);
                mma16816(acc[mi][nb], ah[mi], blp);
                mma16816(acc[mi][nb], al[mi], bhp);
            }
    }

    // ---- epilogue: bias, store, per-column stats ----
    float* outp = (MODE == 1) ? g_Y1 : g_P;
    float cs[4][2], cq[4][2];
#pragma unroll
    for (int nb = 0; nb < 4; nb++) { cs[nb][0] = cs[nb][1] = 0.f; cq[nb][0] = cq[nb][1] = 0.f; }
    float bse[4][2];
#pragma unroll
    for (int nb = 0; nb < 4; nb++) {
        int c = wn * 32 + nb * 8 + (lane & 3) * 2;
        bse[nb][0] = __ldg(bias + c);
        bse[nb][1] = __ldg(bias + c + 1);
    }
#pragma unroll
    for (int mi = 0; mi < 2; mi++) {
        int r0 = m0 + wm * 32 + mi * 16 + (lane >> 2);
        int r1 = r0 + 8;
        bool v0 = r0 < NN, v1 = r1 < NN;
#pragma unroll
        for (int nb = 0; nb < 4; nb++) {
            int c = wn * 32 + nb * 8 + (lane & 3) * 2;
            float o0 = acc[mi][nb][0] + bse[nb][0];
            float o1 = acc[mi][nb][1] + bse[nb][1];
            float o2 = acc[mi][nb][2] + bse[nb][0];
            float o3 = acc[mi][nb][3] + bse[nb][1];
            if (v0) {
                *(float2*)(outp + (size_t)r0 * HH + c) = make_float2(o0, o1);
                cs[nb][0] += o0; cs[nb][1] += o1;
                cq[nb][0] += o0 * o0; cq[nb][1] += o1 * o1;
            }
            if (v1) {
                *(float2*)(outp + (size_t)r1 * HH + c) = make_float2(o2, o3);
                cs[nb][0] += o2; cs[nb][1] += o3;
                cq[nb][0] += o2 * o2; cq[nb][1] += o3 * o3;
            }
        }
    }
#pragma unroll
    for (int nb = 0; nb < 4; nb++) {
#pragma unroll
        for (int j = 0; j < 2; j++) {
            float s = cs[nb][j], q = cq[nb][j];
#pragma unroll
            for (int off = 16; off >= 4; off >>= 1) {
                s += __shfl_down_sync(0xffffffffu, s, off);
                q += __shfl_down_sync(0xffffffffu, q, off);
            }
            if (lane < 4) {
                int c = wn * 32 + nb * 8 + lane * 2 + j;
                sS[wm * HH + c] = s;
                sQ[wm * HH + c] = q;
            }
        }
    }
    __syncthreads();
    if (tid < HH) {
        float s = sS[tid] + sS[HH + tid];
        float q = sQ[tid] + sQ[HH + tid];
        float* st = g_stats + ((MODE == 1) ? 0 : 2 * HH);
        atomicAdd(st + tid, s);
        atomicAdd(st + HH + tid, q);
    }
}

__global__ void k_bnstat(int set) {
    int j = threadIdx.x;
    float s  = g_stats[set * 2 * HH + j];
    float sq = g_stats[set * 2 * HH + HH + j];
    float mu = s * (1.f / (float)NN);
    float var = sq * (1.f / (float)NN) - mu * mu;
    g_bn[set * 2 * HH + j] = mu;
    g_bn[set * 2 * HH + HH + j] = rsqrtf(var + 1e-5f);
}

__global__ void k_pool(const int* __restrict__ batch,
                       const float* __restrict__ bg, const float* __restrict__ bb) {
    int idx = blockIdx.x * blockDim.x + threadIdx.x;
    int n = idx >> 5; if (n >= NN) return;
    int c = (idx & 31) << 2;
    float4 y = *(const float4*)(g_P + (size_t)n * HH + c);
    float s0 = __ldg(bg + c + 0) * g_bn[3 * HH + c + 0];
    float s1 = __ldg(bg + c + 1) * g_bn[3 * HH + c + 1];
    float s2 = __ldg(bg + c + 2) * g_bn[3 * HH + c + 2];
    float s3 = __ldg(bg + c + 3) * g_bn[3 * HH + c + 3];
    float4 o;
    o.x = fmaf(s0, y.x - g_bn[2 * HH + c + 0], __ldg(bb + c + 0));
    o.y = fmaf(s1, y.y - g_bn[2 * HH + c + 1], __ldg(bb + c + 1));
    o.z = fmaf(s2, y.z - g_bn[2 * HH + c + 2], __ldg(bb + c + 2));
    o.w = fmaf(s3, y.w - g_bn[2 * HH + c + 3], __ldg(bb + c + 3));
    red_add_v4(g_pool + (size_t)__ldg(batch + n) * HH + c, o);
}

__global__ void k_final(const float* __restrict__ cw1, const float* __restrict__ cb1,
                        const float* __restrict__ cw2, const float* __restrict__ cb2,
                        float* __restrict__ out) {
    __shared__ float p[HH];
    __shared__ float rb[4];
    int j = threadIdx.x;
    p[j] = g_pool[(size_t)blockIdx.x * HH + j];
    __syncthreads();
    float acc = __ldg(cb1 + j);
#pragma unroll 8
    for (int i = 0; i < HH; i++)
        acc = fmaf(p[i], __ldg(cw1 + i * HH + j), acc);
    float v = fmaxf(acc, 0.f) * __ldg(cw2 + j);
#pragma unroll
    for (int off = 16; off > 0; off >>= 1)
        v += __shfl_down_sync(0xffffffffu, v, off);
    if ((j & 31) == 0) rb[j >> 5] = v;
    __syncthreads();
    if (j == 0) out[blockIdx.x] = rb[0] + rb[1] + rb[2] + rb[3] + __ldg(cb2);
}

extern "C" void kernel_launch(void* const* d_in, const int* in_sizes, int n_in,
                              void* d_out, int out_size) {
    const int*   x     = (const int*)d_in[0];
    const int*   ei    = (const int*)d_in[1];
    const int*   ea    = (const int*)d_in[2];
    const int*   batch = (const int*)d_in[3];
    const float* aemb  = (const float*)d_in[4];
    const float* bemb  = (const float*)d_in[5];
    const float* eps   = (const float*)d_in[6];
    const float* w1    = (const float*)d_in[7];
    const float* b1    = (const float*)d_in[8];
    const float* bn1g  = (const float*)d_in[9];
    const float* bn1b  = (const float*)d_in[10];
    const float* w2    = (const float*)d_in[11];
    const float* b2    = (const float*)d_in[12];
    const float* bng   = (const float*)d_in[13];
    const float* bnb   = (const float*)d_in[14];
    const float* cw1   = (const float*)d_in[15];
    const float* cb1   = (const float*)d_in[16];
    const float* cw2   = (const float*)d_in[17];
    const float* cb2   = (const float*)d_in[18];
    float* out = (float*)d_out;
    const int* row = ei;
    const int* col = ei + EE;

    cudaFuncSetAttribute(k_mma<1>, cudaFuncAttributeMaxDynamicSharedMemorySize, GEMM_SMEM);
    cudaFuncSetAttribute(k_mma<2>, cudaFuncAttributeMaxDynamicSharedMemorySize, GEMM_SMEM);

    const int NT = 256;
    const int gridNH = (NN * 32 + NT - 1) / NT;   // 37500
    const int gridE  = (EE + NT - 1) / NT;
    const int gridGEMM = (NN + 63) / 64;          // 4688
    const int gridNode = (NN + 7) / 8;            // 37500

    k_init<<<2048, NT>>>();
    k_prepw<<<dim3(16, 10), 256>>>(w1, w2);
    k_prepbond<<<dim3(216, 5), HH>>>(bemb);
    k_atom<<<gridNH, NT>>>(x, aemb);
    k_cnt<<<gridE, NT>>>(row, col);
    k_scan<<<2, 1024>>>();
    k_fill<<<gridE, NT>>>(row, col, ea);
    for (int l = 0; l < 5; l++) {
        if (l == 0)
            k_node<1><<<gridNode, NT>>>(0, nullptr, nullptr);
        else
            k_node<0><<<gridNode, NT>>>(l, bng + (l - 1) * HH, bnb + (l - 1) * HH);
        k_mma<1><<<gridGEMM, NT, GEMM_SMEM>>>(2 * l, b1 + l * HH, eps + l, nullptr, nullptr);
        k_bnstat<<<1, HH>>>(0);
        k_mma<2><<<gridGEMM, NT, GEMM_SMEM>>>(2 * l + 1, b2 + l * HH, nullptr,
                                              bn1g + l * HH, bn1b + l * HH);
        k_bnstat<<<1, HH>>>(1);
    }
    k_pool<<<gridNH, NT>>>(batch, bng + 4 * HH, bnb + 4 * HH);
    k_final<<<GG, HH>>>(cw1, cb1, cw2, cb2, out);
}